// round 11
// baseline (speedup 1.0000x reference)
#include <cuda_runtime.h>
#include <math.h>

#define TPB 256

namespace FN {

constexpr int NE = 16;

struct __align__(16) Smem {
  float one[NE * 260];     // one-stream activations (layer0: cols0-15 = raw features)
  float two[256 * 36];     // two-stream activations, row (i*16+j), stride 36
  float wt[2 * 16 * 260];  // double-buffered weight tiles, transposed [fi][o]
  float wwt[32 * 36];      // two-stream weights transposed [f][o]
  float two4[256 * 5];     // layer-0 two features    } det arena alias (2240 floats)
  float f0s[16 * 60];      // layer-0 f vectors       }
  float g1all[512];        // [0:256)=g1u, [256:512)=g1d
  float g2u[512], g2d[512];
  float c[256];
  float bw[32];
  float xx[48], pos[12], rr[64];
  float sg[512], pw[512], eg[128];
};

__device__ __forceinline__ float ftanh(float x) {
  float ax = fabsf(x);
  float e = __expf(-2.0f * ax);
  float t = __fdividef(1.0f - e, 1.0f + e);
  return x >= 0.0f ? t : -t;
}

// ---- staging: 4x LDG.128 (scattered rows) + reg transpose + 4x STS.128 ----
__device__ __forceinline__ void ldg_t16(const float* __restrict__ W, int ldw, int f0, float4* rg) {
  int ob4 = (threadIdx.x & 63) * 4;
  int fb = (threadIdx.x >> 6) * 4;
#pragma unroll
  for (int i = 0; i < 4; i++)
    rg[i] = __ldg((const float4*)(W + (ob4 + i) * ldw + f0 + fb));
}
__device__ __forceinline__ void sts_t16(float* buf, const float4* rg) {
  int ob4 = (threadIdx.x & 63) * 4;
  int fb = (threadIdx.x >> 6) * 4;
  *(float4*)(buf + (fb + 0) * 260 + ob4) = make_float4(rg[0].x, rg[1].x, rg[2].x, rg[3].x);
  *(float4*)(buf + (fb + 1) * 260 + ob4) = make_float4(rg[0].y, rg[1].y, rg[2].y, rg[3].y);
  *(float4*)(buf + (fb + 2) * 260 + ob4) = make_float4(rg[0].z, rg[1].z, rg[2].z, rg[3].z);
  *(float4*)(buf + (fb + 3) * 260 + ob4) = make_float4(rg[0].w, rg[1].w, rg[2].w, rg[3].w);
}

// layer-0 scalar staging (KT=8, 56 real cols, tiny)
__device__ __forceinline__ void ldg0(const float* __restrict__ W, int f0, float* rg) {
#pragma unroll
  for (int e = 0; e < 8; e++) {
    int idx = threadIdx.x + e * TPB;
    int o = idx >> 3, fi = idx & 7;
    int col = f0 + fi;
    rg[e] = (col < 56) ? __ldg(W + o * 56 + col) : 0.0f;
  }
}
__device__ __forceinline__ void sts0(float* buf, const float* rg) {
#pragma unroll
  for (int e = 0; e < 8; e++) {
    int idx = threadIdx.x + e * TPB;
    int o = idx >> 3, fi = idx & 7;
    buf[fi * 260 + o] = rg[e];
  }
}

#define ROW_FMA(RR, AV) do { \
  acc[(RR)*4+0] = fmaf(AV.x, w0.x, acc[(RR)*4+0]); \
  acc[(RR)*4+1] = fmaf(AV.x, w0.y, acc[(RR)*4+1]); \
  acc[(RR)*4+2] = fmaf(AV.x, w0.z, acc[(RR)*4+2]); \
  acc[(RR)*4+3] = fmaf(AV.x, w0.w, acc[(RR)*4+3]); \
  acc[(RR)*4+0] = fmaf(AV.y, w1.x, acc[(RR)*4+0]); \
  acc[(RR)*4+1] = fmaf(AV.y, w1.y, acc[(RR)*4+1]); \
  acc[(RR)*4+2] = fmaf(AV.y, w1.z, acc[(RR)*4+2]); \
  acc[(RR)*4+3] = fmaf(AV.y, w1.w, acc[(RR)*4+3]); \
  acc[(RR)*4+0] = fmaf(AV.z, w2.x, acc[(RR)*4+0]); \
  acc[(RR)*4+1] = fmaf(AV.z, w2.y, acc[(RR)*4+1]); \
  acc[(RR)*4+2] = fmaf(AV.z, w2.z, acc[(RR)*4+2]); \
  acc[(RR)*4+3] = fmaf(AV.z, w2.w, acc[(RR)*4+3]); \
  acc[(RR)*4+0] = fmaf(AV.w, w3.x, acc[(RR)*4+0]); \
  acc[(RR)*4+1] = fmaf(AV.w, w3.y, acc[(RR)*4+1]); \
  acc[(RR)*4+2] = fmaf(AV.w, w3.z, acc[(RR)*4+2]); \
  acc[(RR)*4+3] = fmaf(AV.w, w3.w, acc[(RR)*4+3]); \
} while (0)

// vectorized one-stream GEMM tile: 4 electrons x 4 outputs, float4 acts + float4 weights
template<int KT, int AS>
__device__ __forceinline__ void one_tile_v(const float* buf, const float* act, int ob, float* acc) {
#pragma unroll
  for (int q = 0; q < KT / 4; q++) {
    float4 a0 = *(const float4*)(act + 0 * AS + q * 4);
    float4 a1 = *(const float4*)(act + 1 * AS + q * 4);
    float4 a2 = *(const float4*)(act + 2 * AS + q * 4);
    float4 a3 = *(const float4*)(act + 3 * AS + q * 4);
    float4 w0 = *(const float4*)(buf + (q * 4 + 0) * 260 + ob);
    float4 w1 = *(const float4*)(buf + (q * 4 + 1) * 260 + ob);
    float4 w2 = *(const float4*)(buf + (q * 4 + 2) * 260 + ob);
    float4 w3 = *(const float4*)(buf + (q * 4 + 3) * 260 + ob);
    ROW_FMA(0, a0); ROW_FMA(1, a1); ROW_FMA(2, a2); ROW_FMA(3, a3);
  }
}

__global__ void __launch_bounds__(TPB, 2)
ferminet_kernel(const float* __restrict__ x, const float* __restrict__ nuc,
                const float* __restrict__ v0w, const float* __restrict__ v0b,
                const float* __restrict__ vw,  const float* __restrict__ vb,
                const float* __restrict__ w0w, const float* __restrict__ w0b,
                const float* __restrict__ ww,  const float* __restrict__ wb,
                const float* __restrict__ envw, const float* __restrict__ envg,
                const float* __restrict__ sigma, const float* __restrict__ pi,
                float* __restrict__ out) {
  extern __shared__ float smem_raw[];
  Smem* S = (Smem*)smem_raw;
  const int tid = threadIdx.x;
  const int b = blockIdx.x;
  const int g = tid >> 6;         // electron group (4 electrons), warp-uniform
  const int ob = (tid & 63) * 4;  // output base (4 outputs)
  const int pg = tid >> 2;        // two-stream pair group (pairs pg,64+pg,128+pg,192+pg)
  const int og = (tid & 3) * 8;   // two-stream output base (8 outputs)

  // ---- Phase A: small tensors ----
  if (tid < 48) S->xx[tid] = x[b * 48 + tid];
  if (tid < 12) S->pos[tid] = nuc[tid];
  {
    int q = tid;  // q = (k*8+i)*4+m, i<8; global (k*16+i)*4+m
    S->sg[q] = fabsf(sigma[q + (q >> 5) * 32]);
    S->pw[q] = pi[q + (q >> 5) * 32];
    q = tid + 256;
    S->sg[q] = fabsf(sigma[q + (q >> 5) * 32]);
    S->pw[q] = pi[q + (q >> 5) * 32];
  }
  if (tid < 128) S->eg[tid] = envg[(tid >> 3) * NE + (tid & 7)];
  __syncthreads();

  // ---- Phase B: geometry ----
  {
    int i = tid >> 4, j = tid & 15;
    float dx = S->xx[j * 3 + 0] - S->xx[i * 3 + 0];
    float dy = S->xx[j * 3 + 1] - S->xx[i * 3 + 1];
    float dz = S->xx[j * 3 + 2] - S->xx[i * 3 + 2];
    float ss = dx * dx + dy * dy + dz * dz;
    float nr = ss > 0.0f ? sqrtf(ss) : 0.0f;
    float* t4 = S->two4 + tid * 5;
    t4[0] = dx; t4[1] = dy; t4[2] = dz; t4[3] = nr;
  }
  if (tid < 64) {
    int n = tid >> 2, m = tid & 3;
    float ex = S->xx[n * 3 + 0] - S->pos[m * 3 + 0];
    float ey = S->xx[n * 3 + 1] - S->pos[m * 3 + 1];
    float ez = S->xx[n * 3 + 2] - S->pos[m * 3 + 2];
    float d = sqrtf(ex * ex + ey * ey + ez * ez);
    float* o1 = S->one + n * 260 + m * 4;
    o1[0] = ex; o1[1] = ey; o1[2] = ez; o1[3] = d;
    S->rr[n * 4 + m] = d;
  }
  __syncthreads();

  // ---- Layer 0 ----
  {
    if (tid < 32) {  // g1 means over 16-dim raw one
      int f = tid & 15; bool up = tid < 16;
      float s = 0.0f;
#pragma unroll
      for (int n = 0; n < 8; n++) s += S->one[(up ? n : n + 8) * 260 + f];
      S->g1all[(up ? 0 : 256) + f] = s * 0.125f;
    }
    if (tid < 128) {  // g2 means over 4-dim two4
      int i = tid >> 3, c2 = tid & 7;
      int col = c2 & 3; bool up2 = c2 < 4;
      float s = 0.0f;
#pragma unroll
      for (int j = 0; j < 8; j++) s += S->two4[(i * NE + (up2 ? j : j + 8)) * 5 + col];
      (up2 ? S->g2u : S->g2d)[i * 32 + col] = s * 0.125f;
    }
    // stage two-stream layer-0 weights (transposed [f][o])
    if (tid < 128) S->wwt[(tid & 3) * 36 + (tid >> 2)] = __ldg(w0w + tid);
    if (tid < 32) S->bw[tid] = __ldg(w0b + tid);
    __syncthreads();

    // build f0 vectors [16][60] (pad 56..59 = 0)
#pragma unroll
    for (int e = 0; e < 4; e++) {
      int idx = tid + e * TPB;
      if (idx < 960) {
        int n = idx / 60, cc = idx - n * 60;
        float v;
        if (cc < 16)      v = S->one[n * 260 + cc];
        else if (cc < 32) v = S->g1all[cc - 16];
        else if (cc < 48) v = S->g1all[256 + cc - 32];
        else if (cc < 52) v = S->g2u[n * 32 + (cc - 48)];
        else if (cc < 56) v = S->g2d[n * 32 + (cc - 52)];
        else              v = 0.0f;
        S->f0s[idx] = v;
      }
    }

    float acc[16];
#pragma unroll
    for (int q = 0; q < 16; q++) acc[q] = 0.0f;
    {
      float rg[8];
      ldg0(v0w, 0, rg);
      for (int T = 0; T < 7; T++) {
        float* cur = S->wt + (T & 1) * 4160;
        sts0(cur, rg);
        __syncthreads();
        if (T + 1 < 7) ldg0(v0w, (T + 1) * 8, rg);
        one_tile_v<8, 60>(cur, S->f0s + (g * 4) * 60 + T * 8, ob, acc);
      }
    }
    {
      float4 bb = *(const float4*)(v0b + ob);
#pragma unroll
      for (int r = 0; r < 4; r++) {
        int n = g * 4 + r;
        float4 v;
        v.x = ftanh(acc[r * 4 + 0] + bb.x);
        v.y = ftanh(acc[r * 4 + 1] + bb.y);
        v.z = ftanh(acc[r * 4 + 2] + bb.z);
        v.w = ftanh(acc[r * 4 + 3] + bb.w);
        *(float4*)(S->one + n * 260 + ob) = v;
      }
    }
    // two-stream layer 0 (K=4): 4 pairs x 8 outputs per thread
    {
      float acc2[32];
#pragma unroll
      for (int q = 0; q < 32; q++) acc2[q] = 0.0f;
#pragma unroll
      for (int f = 0; f < 4; f++) {
        float4 w0v = *(const float4*)(S->wwt + f * 36 + og);
        float4 w1v = *(const float4*)(S->wwt + f * 36 + og + 4);
#pragma unroll
        for (int r = 0; r < 4; r++) {
          float av = S->two4[(r * 64 + pg) * 5 + f];
          acc2[r*8+0] = fmaf(av, w0v.x, acc2[r*8+0]);
          acc2[r*8+1] = fmaf(av, w0v.y, acc2[r*8+1]);
          acc2[r*8+2] = fmaf(av, w0v.z, acc2[r*8+2]);
          acc2[r*8+3] = fmaf(av, w0v.w, acc2[r*8+3]);
          acc2[r*8+4] = fmaf(av, w1v.x, acc2[r*8+4]);
          acc2[r*8+5] = fmaf(av, w1v.y, acc2[r*8+5]);
          acc2[r*8+6] = fmaf(av, w1v.z, acc2[r*8+6]);
          acc2[r*8+7] = fmaf(av, w1v.w, acc2[r*8+7]);
        }
      }
      float4 b0 = *(const float4*)(S->bw + og);
      float4 b1 = *(const float4*)(S->bw + og + 4);
#pragma unroll
      for (int r = 0; r < 4; r++) {
        float* rowp = S->two + (r * 64 + pg) * 36 + og;
        float4 v0, v1;
        v0.x = ftanh(acc2[r*8+0] + b0.x); v0.y = ftanh(acc2[r*8+1] + b0.y);
        v0.z = ftanh(acc2[r*8+2] + b0.z); v0.w = ftanh(acc2[r*8+3] + b0.w);
        v1.x = ftanh(acc2[r*8+4] + b1.x); v1.y = ftanh(acc2[r*8+5] + b1.y);
        v1.z = ftanh(acc2[r*8+6] + b1.z); v1.w = ftanh(acc2[r*8+7] + b1.w);
        *(float4*)(rowp) = v0;
        *(float4*)(rowp + 4) = v1;
      }
    }
  }

  // ---- Layers 1..3 ----
  for (int l = 1; l < 4; l++) {
    __syncthreads();
    const float* Wv = vw + (l - 1) * (256 * 832);
    // g means
    {
      float su = 0.0f, sd = 0.0f;
#pragma unroll
      for (int n = 0; n < 8; n++) {
        su += S->one[n * 260 + tid];
        sd += S->one[(n + 8) * 260 + tid];
      }
      S->g1all[tid] = su * 0.125f;
      S->g1all[256 + tid] = sd * 0.125f;
#pragma unroll
      for (int rep = 0; rep < 2; rep++) {
        int idx = tid + rep * TPB;
        int i = idx >> 5, o = idx & 31;
        float a = 0.0f, bb = 0.0f;
#pragma unroll
        for (int j = 0; j < 8; j++) {
          a  += S->two[(i * NE + j) * 36 + o];
          bb += S->two[(i * NE + j + 8) * 36 + o];
        }
        S->g2u[i * 32 + o] = a * 0.125f;
        S->g2d[i * 32 + o] = bb * 0.125f;
      }
    }
    // stage two-stream weights (read much later; barriers in between order it)
    {
      const float* Ww = ww + (l - 1) * 1024;
#pragma unroll
      for (int e = 0; e < 4; e++) {
        int idx = tid + e * TPB;
        S->wwt[(idx & 31) * 36 + (idx >> 5)] = __ldg(Ww + idx);
      }
      if (tid < 32) S->bw[tid] = __ldg(wb + (l - 1) * 32 + tid);
    }
    __syncthreads();

    // row-constant projection c[o]: direct LDG over cols 256..767 (thread = o)
    {
      float c0 = 0.0f, c1 = 0.0f, c2 = 0.0f, c3 = 0.0f;
      const float4* wr = (const float4*)(Wv + tid * 832 + 256);
      const float4* gp = (const float4*)(S->g1all);
#pragma unroll 16
      for (int q = 0; q < 128; q++) {
        float4 w = __ldg(wr + q);
        float4 gg = gp[q];
        c0 = fmaf(w.x, gg.x, c0); c1 = fmaf(w.y, gg.y, c1);
        c2 = fmaf(w.z, gg.z, c2); c3 = fmaf(w.w, gg.w, c3);
      }
      S->c[tid] = (c0 + c1) + (c2 + c3) + __ldg(vb + (l - 1) * 256 + tid);
    }

    // electron GEMM: cols 0..255 (one) + 768..831 (g2)
    float acc[16];
#pragma unroll
    for (int q = 0; q < 16; q++) acc[q] = 0.0f;
    const float* actb = S->one + (g * 4) * 260;
    {
      float4 rg[4];
      ldg_t16(Wv, 832, 0, rg);
      for (int T = 0; T < 20; T++) {
        float* cur = S->wt + (T & 1) * 4160;
        sts_t16(cur, rg);
        __syncthreads();
        int Tn = T + 1;
        if (Tn < 20) {
          int f0 = (Tn < 16) ? Tn * 16 : 768 + (Tn - 16) * 16;
          ldg_t16(Wv, 832, f0, rg);
        }
        if (T < 16) {
          one_tile_v<16, 260>(cur, actb + T * 16, ob, acc);
        } else {
          const float* a2 = ((T < 18) ? S->g2u : S->g2d) + (g * 4) * 32 + ((T & 1) ? 16 : 0);
          one_tile_v<16, 32>(cur, a2, ob, acc);
        }
      }
    }
    // writeback with residual (ordering vs readers guaranteed by tile barriers)
    {
      float4 cc4 = *(const float4*)(S->c + ob);
#pragma unroll
      for (int r = 0; r < 4; r++) {
        int n = g * 4 + r;
        float4 old = *(const float4*)(S->one + n * 260 + ob);
        float4 v;
        v.x = ftanh(acc[r * 4 + 0] + cc4.x) + old.x;
        v.y = ftanh(acc[r * 4 + 1] + cc4.y) + old.y;
        v.z = ftanh(acc[r * 4 + 2] + cc4.z) + old.z;
        v.w = ftanh(acc[r * 4 + 3] + cc4.w) + old.w;
        *(float4*)(S->one + n * 260 + ob) = v;
      }
    }
    // two-stream GEMM (K=32): 4 pairs x 8 outputs, float4 acts + weights
    {
      float acc2[32];
#pragma unroll
      for (int q = 0; q < 32; q++) acc2[q] = 0.0f;
#pragma unroll
      for (int f4 = 0; f4 < 8; f4++) {
        float4 a0 = *(const float4*)(S->two + (0 * 64 + pg) * 36 + f4 * 4);
        float4 a1 = *(const float4*)(S->two + (1 * 64 + pg) * 36 + f4 * 4);
        float4 a2 = *(const float4*)(S->two + (2 * 64 + pg) * 36 + f4 * 4);
        float4 a3 = *(const float4*)(S->two + (3 * 64 + pg) * 36 + f4 * 4);
#pragma unroll
        for (int k = 0; k < 4; k++) {
          int f = f4 * 4 + k;
          float4 wA = *(const float4*)(S->wwt + f * 36 + og);
          float4 wB = *(const float4*)(S->wwt + f * 36 + og + 4);
          float v0 = (k == 0) ? a0.x : (k == 1) ? a0.y : (k == 2) ? a0.z : a0.w;
          float v1 = (k == 0) ? a1.x : (k == 1) ? a1.y : (k == 2) ? a1.z : a1.w;
          float v2 = (k == 0) ? a2.x : (k == 1) ? a2.y : (k == 2) ? a2.z : a2.w;
          float v3 = (k == 0) ? a3.x : (k == 1) ? a3.y : (k == 2) ? a3.z : a3.w;
#define TWO_FMA(RR, AV) \
          acc2[(RR)*8+0] = fmaf(AV, wA.x, acc2[(RR)*8+0]); \
          acc2[(RR)*8+1] = fmaf(AV, wA.y, acc2[(RR)*8+1]); \
          acc2[(RR)*8+2] = fmaf(AV, wA.z, acc2[(RR)*8+2]); \
          acc2[(RR)*8+3] = fmaf(AV, wA.w, acc2[(RR)*8+3]); \
          acc2[(RR)*8+4] = fmaf(AV, wB.x, acc2[(RR)*8+4]); \
          acc2[(RR)*8+5] = fmaf(AV, wB.y, acc2[(RR)*8+5]); \
          acc2[(RR)*8+6] = fmaf(AV, wB.z, acc2[(RR)*8+6]); \
          acc2[(RR)*8+7] = fmaf(AV, wB.w, acc2[(RR)*8+7]);
          TWO_FMA(0, v0) TWO_FMA(1, v1) TWO_FMA(2, v2) TWO_FMA(3, v3)
#undef TWO_FMA
        }
      }
      // threads sharing rows (same pg, different og) are in the same warp:
      // finish all activation reads before any writeback.
      __syncwarp();
      float4 b0 = *(const float4*)(S->bw + og);
      float4 b1 = *(const float4*)(S->bw + og + 4);
#pragma unroll
      for (int r = 0; r < 4; r++) {
        float* rowp = S->two + (r * 64 + pg) * 36 + og;
        float4 o0 = *(const float4*)(rowp);
        float4 o1 = *(const float4*)(rowp + 4);
        o0.x = ftanh(acc2[r*8+0] + b0.x) + o0.x;
        o0.y = ftanh(acc2[r*8+1] + b0.y) + o0.y;
        o0.z = ftanh(acc2[r*8+2] + b0.z) + o0.z;
        o0.w = ftanh(acc2[r*8+3] + b0.w) + o0.w;
        o1.x = ftanh(acc2[r*8+4] + b1.x) + o1.x;
        o1.y = ftanh(acc2[r*8+5] + b1.y) + o1.y;
        o1.z = ftanh(acc2[r*8+6] + b1.z) + o1.z;
        o1.w = ftanh(acc2[r*8+7] + b1.w) + o1.w;
        *(float4*)(rowp) = o0;
        *(float4*)(rowp + 4) = o1;
      }
    }
  }

  __syncthreads();

  // ---- Envelope / orbitals ----
  float* D = S->two4;  // det arena aliases two4+f0s (both dead; 2240 floats)
  {
    int k = tid >> 4, i = (tid >> 1) & 7, jh = tid & 1;
    const float* wrow = envw + (k * 16 + i) * 256;
    float acc[8];
#pragma unroll
    for (int j = 0; j < 8; j++) acc[j] = 0.0f;
    for (int f4 = 0; f4 < 64; f4++) {
      float4 w = __ldg((const float4*)(wrow + f4 * 4));
#pragma unroll
      for (int j = 0; j < 8; j++) {
        float4 a = *(const float4*)(S->one + (jh * 8 + j) * 260 + f4 * 4);
        acc[j] += w.x * a.x + w.y * a.y + w.z * a.z + w.w * a.w;
      }
    }
    float lg = 256.0f * S->eg[k * 8 + i];
    int si = (k * 8 + i) * 4;
    float p0 = S->pw[si], p1 = S->pw[si + 1], p2 = S->pw[si + 2], p3 = S->pw[si + 3];
    float s0 = S->sg[si], s1 = S->sg[si + 1], s2 = S->sg[si + 2], s3 = S->sg[si + 3];
#pragma unroll
    for (int j = 0; j < 8; j++) {
      int col = jh * 8 + j;
      const float* rrow = S->rr + col * 4;
      float env = p0 * __expf(-s0 * rrow[0]) + p1 * __expf(-s1 * rrow[1]) +
                  p2 * __expf(-s2 * rrow[2]) + p3 * __expf(-s3 * rrow[3]);
      D[(jh * 16 + k) * 65 + i * 8 + j] = (acc[j] + lg) * env;
    }
  }
  __syncthreads();

  // ---- Determinants (32 matrices 8x8, pivoted LU) ----
  float* dets = D + 2080;
  float* prods = D + 2112;
  if (tid < 32) {
    float* A = D + tid * 65;
    float dv = 1.0f;
    for (int cph = 0; cph < 8; cph++) {
      int p = cph; float mx = fabsf(A[cph * 8 + cph]);
      for (int r = cph + 1; r < 8; r++) {
        float fv = fabsf(A[r * 8 + cph]);
        if (fv > mx) { mx = fv; p = r; }
      }
      if (mx == 0.0f) { dv = 0.0f; break; }
      if (p != cph) {
#pragma unroll
        for (int cc = 0; cc < 8; cc++) {
          float t = A[cph * 8 + cc]; A[cph * 8 + cc] = A[p * 8 + cc]; A[p * 8 + cc] = t;
        }
        dv = -dv;
      }
      float piv = A[cph * 8 + cph];
      dv *= piv;
      float inv = 1.0f / piv;
      for (int r = cph + 1; r < 8; r++) {
        float m = A[r * 8 + cph] * inv;
        for (int cc = cph + 1; cc < 8; cc++) A[r * 8 + cc] -= m * A[cph * 8 + cc];
      }
    }
    dets[tid] = dv;
  }
  __syncthreads();
  if (tid < 16) prods[tid] = dets[tid] * dets[16 + tid];
  __syncthreads();
  if (tid == 0) {
    float s = 0.0f;
#pragma unroll
    for (int k = 0; k < 16; k++) s += prods[k];
    out[b] = s;
  }
}

}  // namespace FN

extern "C" void kernel_launch(void* const* d_in, const int* in_sizes, int n_in,
                              void* d_out, int out_size) {
  const float* x    = (const float*)d_in[0];
  const float* nuc  = (const float*)d_in[1];
  const float* v0w  = (const float*)d_in[2];
  const float* v0b  = (const float*)d_in[3];
  const float* vw   = (const float*)d_in[4];
  const float* vb   = (const float*)d_in[5];
  const float* w0w  = (const float*)d_in[6];
  const float* w0b  = (const float*)d_in[7];
  const float* ww   = (const float*)d_in[8];
  const float* wb   = (const float*)d_in[9];
  const float* envw = (const float*)d_in[10];
  const float* envg = (const float*)d_in[11];
  const float* sig  = (const float*)d_in[12];
  const float* pi   = (const float*)d_in[13];
  float* out = (float*)d_out;

  int B = in_sizes[0] / 48;
  int smem = (int)sizeof(FN::Smem);
  cudaFuncSetAttribute(FN::ferminet_kernel, cudaFuncAttributeMaxDynamicSharedMemorySize, smem);
  FN::ferminet_kernel<<<B, TPB, smem>>>(x, nuc, v0w, v0b, vw, vb, w0w, w0b, ww, wb,
                                        envw, envg, sig, pi, out);
}

// round 12
// speedup vs baseline: 1.8179x; 1.8179x over previous
#include <cuda_runtime.h>
#include <math.h>

#define TPB 256

namespace FN {

constexpr int NE = 16;

struct __align__(16) Smem {
  float one[NE * 260];     // one-stream activations (layer0: cols0-15 = raw features)
  float two[256 * 36];     // two-stream activations, row (i*16+j), stride 36
  float wt[2 * 16 * 260];  // double-buffered weight tiles, transposed [fi][o]
  float wwt[32 * 36];      // two-stream weights transposed [f][o]
  float two4[256 * 5];     // layer-0 two features    } det arena alias (2240 floats)
  float f0s[16 * 60];      // layer-0 f vectors       }
  float g1all[512];        // [0:256)=g1u, [256:512)=g1d
  float g2u[512], g2d[512];
  float c[256];
  float bw[32];
  float xx[48], pos[12], rr[64];
  float sg[512], pw[512], eg[128];
};

__device__ __forceinline__ float ftanh(float x) {
  float ax = fabsf(x);
  float e = __expf(-2.0f * ax);
  float t = __fdividef(1.0f - e, 1.0f + e);
  return x >= 0.0f ? t : -t;
}

// ---- staging: coalesced vectorized LDG (lanes read contiguous along the row),
//      transposed scalar STS into [fi][o] buffer (stride 260, ~2-way conflicts) ----
__device__ __forceinline__ void ldg_t16(const float* __restrict__ W, int ldw, int f0, float4* rg) {
#pragma unroll
  for (int e = 0; e < 4; e++) {
    int j = threadIdx.x + e * TPB;     // j in [0,1024): o = j>>2, fq = j&3
    int o = j >> 2, fq = j & 3;
    rg[e] = __ldg((const float4*)(W + o * ldw + f0 + fq * 4));
  }
}
__device__ __forceinline__ void sts_t16(float* buf, const float4* rg) {
#pragma unroll
  for (int e = 0; e < 4; e++) {
    int j = threadIdx.x + e * TPB;
    int o = j >> 2, fq = j & 3;
    buf[(fq * 4 + 0) * 260 + o] = rg[e].x;
    buf[(fq * 4 + 1) * 260 + o] = rg[e].y;
    buf[(fq * 4 + 2) * 260 + o] = rg[e].z;
    buf[(fq * 4 + 3) * 260 + o] = rg[e].w;
  }
}

// layer-0 scalar staging (KT=8, 56 real cols, tiny, coalesced)
__device__ __forceinline__ void ldg0(const float* __restrict__ W, int f0, float* rg) {
#pragma unroll
  for (int e = 0; e < 8; e++) {
    int idx = threadIdx.x + e * TPB;
    int o = idx >> 3, fi = idx & 7;
    int col = f0 + fi;
    rg[e] = (col < 56) ? __ldg(W + o * 56 + col) : 0.0f;
  }
}
__device__ __forceinline__ void sts0(float* buf, const float* rg) {
#pragma unroll
  for (int e = 0; e < 8; e++) {
    int idx = threadIdx.x + e * TPB;
    int o = idx >> 3, fi = idx & 7;
    buf[fi * 260 + o] = rg[e];
  }
}

#define ROW_FMA(RR, AV) do { \
  acc[(RR)*4+0] = fmaf(AV.x, w0.x, acc[(RR)*4+0]); \
  acc[(RR)*4+1] = fmaf(AV.x, w0.y, acc[(RR)*4+1]); \
  acc[(RR)*4+2] = fmaf(AV.x, w0.z, acc[(RR)*4+2]); \
  acc[(RR)*4+3] = fmaf(AV.x, w0.w, acc[(RR)*4+3]); \
  acc[(RR)*4+0] = fmaf(AV.y, w1.x, acc[(RR)*4+0]); \
  acc[(RR)*4+1] = fmaf(AV.y, w1.y, acc[(RR)*4+1]); \
  acc[(RR)*4+2] = fmaf(AV.y, w1.z, acc[(RR)*4+2]); \
  acc[(RR)*4+3] = fmaf(AV.y, w1.w, acc[(RR)*4+3]); \
  acc[(RR)*4+0] = fmaf(AV.z, w2.x, acc[(RR)*4+0]); \
  acc[(RR)*4+1] = fmaf(AV.z, w2.y, acc[(RR)*4+1]); \
  acc[(RR)*4+2] = fmaf(AV.z, w2.z, acc[(RR)*4+2]); \
  acc[(RR)*4+3] = fmaf(AV.z, w2.w, acc[(RR)*4+3]); \
  acc[(RR)*4+0] = fmaf(AV.w, w3.x, acc[(RR)*4+0]); \
  acc[(RR)*4+1] = fmaf(AV.w, w3.y, acc[(RR)*4+1]); \
  acc[(RR)*4+2] = fmaf(AV.w, w3.z, acc[(RR)*4+2]); \
  acc[(RR)*4+3] = fmaf(AV.w, w3.w, acc[(RR)*4+3]); \
} while (0)

// vectorized one-stream GEMM tile: 4 electrons x 4 outputs, float4 acts + float4 weights
template<int KT, int AS>
__device__ __forceinline__ void one_tile_v(const float* buf, const float* act, int ob, float* acc) {
#pragma unroll
  for (int q = 0; q < KT / 4; q++) {
    float4 a0 = *(const float4*)(act + 0 * AS + q * 4);
    float4 a1 = *(const float4*)(act + 1 * AS + q * 4);
    float4 a2 = *(const float4*)(act + 2 * AS + q * 4);
    float4 a3 = *(const float4*)(act + 3 * AS + q * 4);
    float4 w0 = *(const float4*)(buf + (q * 4 + 0) * 260 + ob);
    float4 w1 = *(const float4*)(buf + (q * 4 + 1) * 260 + ob);
    float4 w2 = *(const float4*)(buf + (q * 4 + 2) * 260 + ob);
    float4 w3 = *(const float4*)(buf + (q * 4 + 3) * 260 + ob);
    ROW_FMA(0, a0); ROW_FMA(1, a1); ROW_FMA(2, a2); ROW_FMA(3, a3);
  }
}

__global__ void __launch_bounds__(TPB, 2)
ferminet_kernel(const float* __restrict__ x, const float* __restrict__ nuc,
                const float* __restrict__ v0w, const float* __restrict__ v0b,
                const float* __restrict__ vw,  const float* __restrict__ vb,
                const float* __restrict__ w0w, const float* __restrict__ w0b,
                const float* __restrict__ ww,  const float* __restrict__ wb,
                const float* __restrict__ envw, const float* __restrict__ envg,
                const float* __restrict__ sigma, const float* __restrict__ pi,
                float* __restrict__ out) {
  extern __shared__ float smem_raw[];
  Smem* S = (Smem*)smem_raw;
  const int tid = threadIdx.x;
  const int b = blockIdx.x;
  const int g = tid >> 6;         // electron group (4 electrons), warp-uniform
  const int ob = (tid & 63) * 4;  // output base (4 outputs)
  const int pg = tid >> 2;        // two-stream pair group
  const int og = (tid & 3) * 8;   // two-stream output base (8 outputs)

  // ---- Phase A: small tensors ----
  if (tid < 48) S->xx[tid] = x[b * 48 + tid];
  if (tid < 12) S->pos[tid] = nuc[tid];
  {
    int q = tid;  // q = (k*8+i)*4+m, i<8; global (k*16+i)*4+m
    S->sg[q] = fabsf(sigma[q + (q >> 5) * 32]);
    S->pw[q] = pi[q + (q >> 5) * 32];
    q = tid + 256;
    S->sg[q] = fabsf(sigma[q + (q >> 5) * 32]);
    S->pw[q] = pi[q + (q >> 5) * 32];
  }
  if (tid < 128) S->eg[tid] = envg[(tid >> 3) * NE + (tid & 7)];
  __syncthreads();

  // ---- Phase B: geometry ----
  {
    int i = tid >> 4, j = tid & 15;
    float dx = S->xx[j * 3 + 0] - S->xx[i * 3 + 0];
    float dy = S->xx[j * 3 + 1] - S->xx[i * 3 + 1];
    float dz = S->xx[j * 3 + 2] - S->xx[i * 3 + 2];
    float ss = dx * dx + dy * dy + dz * dz;
    float nr = ss > 0.0f ? sqrtf(ss) : 0.0f;
    float* t4 = S->two4 + tid * 5;
    t4[0] = dx; t4[1] = dy; t4[2] = dz; t4[3] = nr;
  }
  if (tid < 64) {
    int n = tid >> 2, m = tid & 3;
    float ex = S->xx[n * 3 + 0] - S->pos[m * 3 + 0];
    float ey = S->xx[n * 3 + 1] - S->pos[m * 3 + 1];
    float ez = S->xx[n * 3 + 2] - S->pos[m * 3 + 2];
    float d = sqrtf(ex * ex + ey * ey + ez * ez);
    float* o1 = S->one + n * 260 + m * 4;
    o1[0] = ex; o1[1] = ey; o1[2] = ez; o1[3] = d;
    S->rr[n * 4 + m] = d;
  }
  __syncthreads();

  // ---- Layer 0 ----
  {
    if (tid < 32) {  // g1 means over 16-dim raw one
      int f = tid & 15; bool up = tid < 16;
      float s = 0.0f;
#pragma unroll
      for (int n = 0; n < 8; n++) s += S->one[(up ? n : n + 8) * 260 + f];
      S->g1all[(up ? 0 : 256) + f] = s * 0.125f;
    }
    if (tid < 128) {  // g2 means over 4-dim two4
      int i = tid >> 3, c2 = tid & 7;
      int col = c2 & 3; bool up2 = c2 < 4;
      float s = 0.0f;
#pragma unroll
      for (int j = 0; j < 8; j++) s += S->two4[(i * NE + (up2 ? j : j + 8)) * 5 + col];
      (up2 ? S->g2u : S->g2d)[i * 32 + col] = s * 0.125f;
    }
    // stage two-stream layer-0 weights (transposed [f][o])
    if (tid < 128) S->wwt[(tid & 3) * 36 + (tid >> 2)] = __ldg(w0w + tid);
    if (tid < 32) S->bw[tid] = __ldg(w0b + tid);
    __syncthreads();

    // build f0 vectors [16][60] (pad 56..59 = 0)
#pragma unroll
    for (int e = 0; e < 4; e++) {
      int idx = tid + e * TPB;
      if (idx < 960) {
        int n = idx / 60, cc = idx - n * 60;
        float v;
        if (cc < 16)      v = S->one[n * 260 + cc];
        else if (cc < 32) v = S->g1all[cc - 16];
        else if (cc < 48) v = S->g1all[256 + cc - 32];
        else if (cc < 52) v = S->g2u[n * 32 + (cc - 48)];
        else if (cc < 56) v = S->g2d[n * 32 + (cc - 52)];
        else              v = 0.0f;
        S->f0s[idx] = v;
      }
    }

    float acc[16];
#pragma unroll
    for (int q = 0; q < 16; q++) acc[q] = 0.0f;
    {
      float rg[8];
      ldg0(v0w, 0, rg);
      for (int T = 0; T < 7; T++) {
        float* cur = S->wt + (T & 1) * 4160;
        sts0(cur, rg);
        __syncthreads();
        if (T + 1 < 7) ldg0(v0w, (T + 1) * 8, rg);
        one_tile_v<8, 60>(cur, S->f0s + (g * 4) * 60 + T * 8, ob, acc);
      }
    }
    {
      float4 bb = *(const float4*)(v0b + ob);
#pragma unroll
      for (int r = 0; r < 4; r++) {
        int n = g * 4 + r;
        float4 v;
        v.x = ftanh(acc[r * 4 + 0] + bb.x);
        v.y = ftanh(acc[r * 4 + 1] + bb.y);
        v.z = ftanh(acc[r * 4 + 2] + bb.z);
        v.w = ftanh(acc[r * 4 + 3] + bb.w);
        *(float4*)(S->one + n * 260 + ob) = v;
      }
    }
    // two-stream layer 0 (K=4): 4 pairs x 8 outputs per thread
    {
      float acc2[32];
#pragma unroll
      for (int q = 0; q < 32; q++) acc2[q] = 0.0f;
#pragma unroll
      for (int f = 0; f < 4; f++) {
        float4 w0v = *(const float4*)(S->wwt + f * 36 + og);
        float4 w1v = *(const float4*)(S->wwt + f * 36 + og + 4);
#pragma unroll
        for (int r = 0; r < 4; r++) {
          float av = S->two4[(r * 64 + pg) * 5 + f];
          acc2[r*8+0] = fmaf(av, w0v.x, acc2[r*8+0]);
          acc2[r*8+1] = fmaf(av, w0v.y, acc2[r*8+1]);
          acc2[r*8+2] = fmaf(av, w0v.z, acc2[r*8+2]);
          acc2[r*8+3] = fmaf(av, w0v.w, acc2[r*8+3]);
          acc2[r*8+4] = fmaf(av, w1v.x, acc2[r*8+4]);
          acc2[r*8+5] = fmaf(av, w1v.y, acc2[r*8+5]);
          acc2[r*8+6] = fmaf(av, w1v.z, acc2[r*8+6]);
          acc2[r*8+7] = fmaf(av, w1v.w, acc2[r*8+7]);
        }
      }
      float4 b0 = *(const float4*)(S->bw + og);
      float4 b1 = *(const float4*)(S->bw + og + 4);
#pragma unroll
      for (int r = 0; r < 4; r++) {
        float* rowp = S->two + (r * 64 + pg) * 36 + og;
        float4 v0, v1;
        v0.x = ftanh(acc2[r*8+0] + b0.x); v0.y = ftanh(acc2[r*8+1] + b0.y);
        v0.z = ftanh(acc2[r*8+2] + b0.z); v0.w = ftanh(acc2[r*8+3] + b0.w);
        v1.x = ftanh(acc2[r*8+4] + b1.x); v1.y = ftanh(acc2[r*8+5] + b1.y);
        v1.z = ftanh(acc2[r*8+6] + b1.z); v1.w = ftanh(acc2[r*8+7] + b1.w);
        *(float4*)(rowp) = v0;
        *(float4*)(rowp + 4) = v1;
      }
    }
  }

  // ---- Layers 1..3 ----
  for (int l = 1; l < 4; l++) {
    __syncthreads();
    const float* Wv = vw + (l - 1) * (256 * 832);
    // g means
    {
      float su = 0.0f, sd = 0.0f;
#pragma unroll
      for (int n = 0; n < 8; n++) {
        su += S->one[n * 260 + tid];
        sd += S->one[(n + 8) * 260 + tid];
      }
      S->g1all[tid] = su * 0.125f;
      S->g1all[256 + tid] = sd * 0.125f;
#pragma unroll
      for (int rep = 0; rep < 2; rep++) {
        int idx = tid + rep * TPB;
        int i = idx >> 5, o = idx & 31;
        float a = 0.0f, bb = 0.0f;
#pragma unroll
        for (int j = 0; j < 8; j++) {
          a  += S->two[(i * NE + j) * 36 + o];
          bb += S->two[(i * NE + j + 8) * 36 + o];
        }
        S->g2u[i * 32 + o] = a * 0.125f;
        S->g2d[i * 32 + o] = bb * 0.125f;
      }
    }
    // stage two-stream weights (read much later; barriers in between order it)
    {
      const float* Ww = ww + (l - 1) * 1024;
#pragma unroll
      for (int e = 0; e < 4; e++) {
        int idx = tid + e * TPB;
        S->wwt[(idx & 31) * 36 + (idx >> 5)] = __ldg(Ww + idx);
      }
      if (tid < 32) S->bw[tid] = __ldg(wb + (l - 1) * 32 + tid);
    }
    __syncthreads();

    // row-constant projection c[o] over g1 cols 256..767:
    // one warp per 32 rows; lanes read 512B of the row contiguously (coalesced),
    // g preloaded to registers; butterfly-shuffle reduction. No smem staging.
    {
      int warp = tid >> 5, lane = tid & 31;
      float4 gv0 = *(const float4*)(S->g1all + 0 * 128 + lane * 4);
      float4 gv1 = *(const float4*)(S->g1all + 1 * 128 + lane * 4);
      float4 gv2 = *(const float4*)(S->g1all + 2 * 128 + lane * 4);
      float4 gv3 = *(const float4*)(S->g1all + 3 * 128 + lane * 4);
#pragma unroll 2
      for (int rr = 0; rr < 32; rr++) {
        int row = warp * 32 + rr;
        const float* wrow = Wv + row * 832 + 256 + lane * 4;
        float4 w0 = __ldg((const float4*)(wrow));
        float4 w1 = __ldg((const float4*)(wrow + 128));
        float4 w2 = __ldg((const float4*)(wrow + 256));
        float4 w3 = __ldg((const float4*)(wrow + 384));
        float s0 = w0.x * gv0.x + w0.y * gv0.y + w0.z * gv0.z + w0.w * gv0.w;
        float s1 = w1.x * gv1.x + w1.y * gv1.y + w1.z * gv1.z + w1.w * gv1.w;
        float s2 = w2.x * gv2.x + w2.y * gv2.y + w2.z * gv2.z + w2.w * gv2.w;
        float s3 = w3.x * gv3.x + w3.y * gv3.y + w3.z * gv3.z + w3.w * gv3.w;
        float s = (s0 + s1) + (s2 + s3);
#pragma unroll
        for (int off = 16; off; off >>= 1) s += __shfl_xor_sync(0xffffffffu, s, off);
        if (lane == 0) S->c[row] = s + __ldg(vb + (l - 1) * 256 + row);
      }
    }

    // electron GEMM: cols 0..255 (one) + 768..831 (g2)
    float acc[16];
#pragma unroll
    for (int q = 0; q < 16; q++) acc[q] = 0.0f;
    const float* actb = S->one + (g * 4) * 260;
    {
      float4 rg[4];
      ldg_t16(Wv, 832, 0, rg);
      for (int T = 0; T < 20; T++) {
        float* cur = S->wt + (T & 1) * 4160;
        sts_t16(cur, rg);
        __syncthreads();
        int Tn = T + 1;
        if (Tn < 20) {
          int f0 = (Tn < 16) ? Tn * 16 : 768 + (Tn - 16) * 16;
          ldg_t16(Wv, 832, f0, rg);
        }
        if (T < 16) {
          one_tile_v<16, 260>(cur, actb + T * 16, ob, acc);
        } else {
          const float* a2 = ((T < 18) ? S->g2u : S->g2d) + (g * 4) * 32 + ((T & 1) ? 16 : 0);
          one_tile_v<16, 32>(cur, a2, ob, acc);
        }
      }
    }
    // writeback with residual (c written pre-loop; tile barriers order it)
    {
      float4 cc4 = *(const float4*)(S->c + ob);
#pragma unroll
      for (int r = 0; r < 4; r++) {
        int n = g * 4 + r;
        float4 old = *(const float4*)(S->one + n * 260 + ob);
        float4 v;
        v.x = ftanh(acc[r * 4 + 0] + cc4.x) + old.x;
        v.y = ftanh(acc[r * 4 + 1] + cc4.y) + old.y;
        v.z = ftanh(acc[r * 4 + 2] + cc4.z) + old.z;
        v.w = ftanh(acc[r * 4 + 3] + cc4.w) + old.w;
        *(float4*)(S->one + n * 260 + ob) = v;
      }
    }
    // two-stream GEMM (K=32): 4 pairs x 8 outputs, float4 acts + weights
    {
      float acc2[32];
#pragma unroll
      for (int q = 0; q < 32; q++) acc2[q] = 0.0f;
#pragma unroll
      for (int f4 = 0; f4 < 8; f4++) {
        float4 a0 = *(const float4*)(S->two + (0 * 64 + pg) * 36 + f4 * 4);
        float4 a1 = *(const float4*)(S->two + (1 * 64 + pg) * 36 + f4 * 4);
        float4 a2 = *(const float4*)(S->two + (2 * 64 + pg) * 36 + f4 * 4);
        float4 a3 = *(const float4*)(S->two + (3 * 64 + pg) * 36 + f4 * 4);
#pragma unroll
        for (int k = 0; k < 4; k++) {
          int f = f4 * 4 + k;
          float4 wA = *(const float4*)(S->wwt + f * 36 + og);
          float4 wB = *(const float4*)(S->wwt + f * 36 + og + 4);
          float v0 = (k == 0) ? a0.x : (k == 1) ? a0.y : (k == 2) ? a0.z : a0.w;
          float v1 = (k == 0) ? a1.x : (k == 1) ? a1.y : (k == 2) ? a1.z : a1.w;
          float v2 = (k == 0) ? a2.x : (k == 1) ? a2.y : (k == 2) ? a2.z : a2.w;
          float v3 = (k == 0) ? a3.x : (k == 1) ? a3.y : (k == 2) ? a3.z : a3.w;
#define TWO_FMA(RR, AV) \
          acc2[(RR)*8+0] = fmaf(AV, wA.x, acc2[(RR)*8+0]); \
          acc2[(RR)*8+1] = fmaf(AV, wA.y, acc2[(RR)*8+1]); \
          acc2[(RR)*8+2] = fmaf(AV, wA.z, acc2[(RR)*8+2]); \
          acc2[(RR)*8+3] = fmaf(AV, wA.w, acc2[(RR)*8+3]); \
          acc2[(RR)*8+4] = fmaf(AV, wB.x, acc2[(RR)*8+4]); \
          acc2[(RR)*8+5] = fmaf(AV, wB.y, acc2[(RR)*8+5]); \
          acc2[(RR)*8+6] = fmaf(AV, wB.z, acc2[(RR)*8+6]); \
          acc2[(RR)*8+7] = fmaf(AV, wB.w, acc2[(RR)*8+7]);
          TWO_FMA(0, v0) TWO_FMA(1, v1) TWO_FMA(2, v2) TWO_FMA(3, v3)
#undef TWO_FMA
        }
      }
      // row-sharing threads (same pg) are warp-local: finish reads before writeback
      __syncwarp();
      float4 b0 = *(const float4*)(S->bw + og);
      float4 b1 = *(const float4*)(S->bw + og + 4);
#pragma unroll
      for (int r = 0; r < 4; r++) {
        float* rowp = S->two + (r * 64 + pg) * 36 + og;
        float4 o0 = *(const float4*)(rowp);
        float4 o1 = *(const float4*)(rowp + 4);
        o0.x = ftanh(acc2[r*8+0] + b0.x) + o0.x;
        o0.y = ftanh(acc2[r*8+1] + b0.y) + o0.y;
        o0.z = ftanh(acc2[r*8+2] + b0.z) + o0.z;
        o0.w = ftanh(acc2[r*8+3] + b0.w) + o0.w;
        o1.x = ftanh(acc2[r*8+4] + b1.x) + o1.x;
        o1.y = ftanh(acc2[r*8+5] + b1.y) + o1.y;
        o1.z = ftanh(acc2[r*8+6] + b1.z) + o1.z;
        o1.w = ftanh(acc2[r*8+7] + b1.w) + o1.w;
        *(float4*)(rowp) = o0;
        *(float4*)(rowp + 4) = o1;
      }
    }
  }

  __syncthreads();

  // ---- Envelope / orbitals ----
  float* D = S->two4;  // det arena aliases two4+f0s (both dead; 2240 floats)
  {
    int k = tid >> 4, i = (tid >> 1) & 7, jh = tid & 1;
    const float* wrow = envw + (k * 16 + i) * 256;
    float acc[8];
#pragma unroll
    for (int j = 0; j < 8; j++) acc[j] = 0.0f;
    for (int f4 = 0; f4 < 64; f4++) {
      float4 w = __ldg((const float4*)(wrow + f4 * 4));
#pragma unroll
      for (int j = 0; j < 8; j++) {
        float4 a = *(const float4*)(S->one + (jh * 8 + j) * 260 + f4 * 4);
        acc[j] += w.x * a.x + w.y * a.y + w.z * a.z + w.w * a.w;
      }
    }
    float lg = 256.0f * S->eg[k * 8 + i];
    int si = (k * 8 + i) * 4;
    float p0 = S->pw[si], p1 = S->pw[si + 1], p2 = S->pw[si + 2], p3 = S->pw[si + 3];
    float s0 = S->sg[si], s1 = S->sg[si + 1], s2 = S->sg[si + 2], s3 = S->sg[si + 3];
#pragma unroll
    for (int j = 0; j < 8; j++) {
      int col = jh * 8 + j;
      const float* rrow = S->rr + col * 4;
      float env = p0 * __expf(-s0 * rrow[0]) + p1 * __expf(-s1 * rrow[1]) +
                  p2 * __expf(-s2 * rrow[2]) + p3 * __expf(-s3 * rrow[3]);
      D[(jh * 16 + k) * 65 + i * 8 + j] = (acc[j] + lg) * env;
    }
  }
  __syncthreads();

  // ---- Determinants (32 matrices 8x8, pivoted LU) ----
  float* dets = D + 2080;
  float* prods = D + 2112;
  if (tid < 32) {
    float* A = D + tid * 65;
    float dv = 1.0f;
    for (int cph = 0; cph < 8; cph++) {
      int p = cph; float mx = fabsf(A[cph * 8 + cph]);
      for (int r = cph + 1; r < 8; r++) {
        float fv = fabsf(A[r * 8 + cph]);
        if (fv > mx) { mx = fv; p = r; }
      }
      if (mx == 0.0f) { dv = 0.0f; break; }
      if (p != cph) {
#pragma unroll
        for (int cc = 0; cc < 8; cc++) {
          float t = A[cph * 8 + cc]; A[cph * 8 + cc] = A[p * 8 + cc]; A[p * 8 + cc] = t;
        }
        dv = -dv;
      }
      float piv = A[cph * 8 + cph];
      dv *= piv;
      float inv = 1.0f / piv;
      for (int r = cph + 1; r < 8; r++) {
        float m = A[r * 8 + cph] * inv;
        for (int cc = cph + 1; cc < 8; cc++) A[r * 8 + cc] -= m * A[cph * 8 + cc];
      }
    }
    dets[tid] = dv;
  }
  __syncthreads();
  if (tid < 16) prods[tid] = dets[tid] * dets[16 + tid];
  __syncthreads();
  if (tid == 0) {
    float s = 0.0f;
#pragma unroll
    for (int k = 0; k < 16; k++) s += prods[k];
    out[b] = s;
  }
}

}  // namespace FN

extern "C" void kernel_launch(void* const* d_in, const int* in_sizes, int n_in,
                              void* d_out, int out_size) {
  const float* x    = (const float*)d_in[0];
  const float* nuc  = (const float*)d_in[1];
  const float* v0w  = (const float*)d_in[2];
  const float* v0b  = (const float*)d_in[3];
  const float* vw   = (const float*)d_in[4];
  const float* vb   = (const float*)d_in[5];
  const float* w0w  = (const float*)d_in[6];
  const float* w0b  = (const float*)d_in[7];
  const float* ww   = (const float*)d_in[8];
  const float* wb   = (const float*)d_in[9];
  const float* envw = (const float*)d_in[10];
  const float* envg = (const float*)d_in[11];
  const float* sig  = (const float*)d_in[12];
  const float* pi   = (const float*)d_in[13];
  float* out = (float*)d_out;

  int B = in_sizes[0] / 48;
  int smem = (int)sizeof(FN::Smem);
  cudaFuncSetAttribute(FN::ferminet_kernel, cudaFuncAttributeMaxDynamicSharedMemorySize, smem);
  FN::ferminet_kernel<<<B, TPB, smem>>>(x, nuc, v0w, v0b, vw, vb, w0w, w0b, ww, wb,
                                        envw, envg, sig, pi, out);
}

// round 13
// speedup vs baseline: 2.0035x; 1.1021x over previous
#include <cuda_runtime.h>
#include <math.h>

#define TPB 256

namespace FN {

constexpr int NE = 16;

// per-batch arena
struct __align__(16) SmemB {
  float one[NE * 260];   // one-stream activations
  float two[256 * 36];   // two-stream activations, row (i*16+j)
  float two4[256 * 5];   // layer-0 two features } det arena alias (2240 floats)
  float f0s[16 * 60];    // layer-0 f vectors    }
  float g1all[512];      // [0:256)=g1u, [256:512)=g1d
  float g2u[512], g2d[512];
  float c[256];
  float xx[48], rr[64];
};
// shared arena (batch-independent)
struct __align__(16) SmemS {
  float wt[2 * 16 * 260];  // double-buffered weight tiles, transposed [fi][o]
  float wwt[32 * 36];      // two-stream weights transposed [f][o]
  float bw[32];
  float pos[16];
  float sg[512], pw[512], eg[128];
};

__device__ __forceinline__ float ftanh(float x) {
  float ax = fabsf(x);
  float e = __expf(-2.0f * ax);
  float t = __fdividef(1.0f - e, 1.0f + e);
  return x >= 0.0f ? t : -t;
}

// ---- staging: coalesced vectorized LDG, transposed scalar STS ----
__device__ __forceinline__ void ldg_t16(const float* __restrict__ W, int ldw, int f0, float4* rg) {
#pragma unroll
  for (int e = 0; e < 4; e++) {
    int j = threadIdx.x + e * TPB;
    int o = j >> 2, fq = j & 3;
    rg[e] = __ldg((const float4*)(W + o * ldw + f0 + fq * 4));
  }
}
__device__ __forceinline__ void sts_t16(float* buf, const float4* rg) {
#pragma unroll
  for (int e = 0; e < 4; e++) {
    int j = threadIdx.x + e * TPB;
    int o = j >> 2, fq = j & 3;
    buf[(fq * 4 + 0) * 260 + o] = rg[e].x;
    buf[(fq * 4 + 1) * 260 + o] = rg[e].y;
    buf[(fq * 4 + 2) * 260 + o] = rg[e].z;
    buf[(fq * 4 + 3) * 260 + o] = rg[e].w;
  }
}
// layer-0 scalar staging (KT=8, 56 real cols)
__device__ __forceinline__ void ldg0(const float* __restrict__ W, int f0, float* rg) {
#pragma unroll
  for (int e = 0; e < 8; e++) {
    int idx = threadIdx.x + e * TPB;
    int o = idx >> 3, fi = idx & 7;
    int col = f0 + fi;
    rg[e] = (col < 56) ? __ldg(W + o * 56 + col) : 0.0f;
  }
}
__device__ __forceinline__ void sts0(float* buf, const float* rg) {
#pragma unroll
  for (int e = 0; e < 8; e++) {
    int idx = threadIdx.x + e * TPB;
    int o = idx >> 3, fi = idx & 7;
    buf[fi * 260 + o] = rg[e];
  }
}

#define RF(ACC, RR, AV) do { \
  ACC[(RR)*4+0] = fmaf(AV.x, w0.x, ACC[(RR)*4+0]); \
  ACC[(RR)*4+1] = fmaf(AV.x, w0.y, ACC[(RR)*4+1]); \
  ACC[(RR)*4+2] = fmaf(AV.x, w0.z, ACC[(RR)*4+2]); \
  ACC[(RR)*4+3] = fmaf(AV.x, w0.w, ACC[(RR)*4+3]); \
  ACC[(RR)*4+0] = fmaf(AV.y, w1.x, ACC[(RR)*4+0]); \
  ACC[(RR)*4+1] = fmaf(AV.y, w1.y, ACC[(RR)*4+1]); \
  ACC[(RR)*4+2] = fmaf(AV.y, w1.z, ACC[(RR)*4+2]); \
  ACC[(RR)*4+3] = fmaf(AV.y, w1.w, ACC[(RR)*4+3]); \
  ACC[(RR)*4+0] = fmaf(AV.z, w2.x, ACC[(RR)*4+0]); \
  ACC[(RR)*4+1] = fmaf(AV.z, w2.y, ACC[(RR)*4+1]); \
  ACC[(RR)*4+2] = fmaf(AV.z, w2.z, ACC[(RR)*4+2]); \
  ACC[(RR)*4+3] = fmaf(AV.z, w2.w, ACC[(RR)*4+3]); \
  ACC[(RR)*4+0] = fmaf(AV.w, w3.x, ACC[(RR)*4+0]); \
  ACC[(RR)*4+1] = fmaf(AV.w, w3.y, ACC[(RR)*4+1]); \
  ACC[(RR)*4+2] = fmaf(AV.w, w3.z, ACC[(RR)*4+2]); \
  ACC[(RR)*4+3] = fmaf(AV.w, w3.w, ACC[(RR)*4+3]); \
} while (0)

// dual-batch one-stream GEMM tile: weights loaded ONCE, used for both batches
template<int KT, int AS>
__device__ __forceinline__ void one_tile_v2(const float* buf,
                                            const float* actA, const float* actB,
                                            int ob, float* accA, float* accB) {
#pragma unroll
  for (int q = 0; q < KT / 4; q++) {
    float4 w0 = *(const float4*)(buf + (q * 4 + 0) * 260 + ob);
    float4 w1 = *(const float4*)(buf + (q * 4 + 1) * 260 + ob);
    float4 w2 = *(const float4*)(buf + (q * 4 + 2) * 260 + ob);
    float4 w3 = *(const float4*)(buf + (q * 4 + 3) * 260 + ob);
    {
      float4 a0 = *(const float4*)(actA + 0 * AS + q * 4);
      float4 a1 = *(const float4*)(actA + 1 * AS + q * 4);
      float4 a2 = *(const float4*)(actA + 2 * AS + q * 4);
      float4 a3 = *(const float4*)(actA + 3 * AS + q * 4);
      RF(accA, 0, a0); RF(accA, 1, a1); RF(accA, 2, a2); RF(accA, 3, a3);
    }
    {
      float4 a0 = *(const float4*)(actB + 0 * AS + q * 4);
      float4 a1 = *(const float4*)(actB + 1 * AS + q * 4);
      float4 a2 = *(const float4*)(actB + 2 * AS + q * 4);
      float4 a3 = *(const float4*)(actB + 3 * AS + q * 4);
      RF(accB, 0, a0); RF(accB, 1, a1); RF(accB, 2, a2); RF(accB, 3, a3);
    }
  }
}

__global__ void __launch_bounds__(TPB, 1)
ferminet_kernel(const float* __restrict__ x, const float* __restrict__ nuc,
                const float* __restrict__ v0w, const float* __restrict__ v0b,
                const float* __restrict__ vw,  const float* __restrict__ vb,
                const float* __restrict__ w0w, const float* __restrict__ w0b,
                const float* __restrict__ ww,  const float* __restrict__ wb,
                const float* __restrict__ envw, const float* __restrict__ envg,
                const float* __restrict__ sigma, const float* __restrict__ pi,
                float* __restrict__ out) {
  extern __shared__ float smem_raw[];
  SmemS* SS = (SmemS*)smem_raw;
  SmemB* SB = (SmemB*)(smem_raw + sizeof(SmemS) / 4);
  SmemB* P0 = SB;
  SmemB* P1 = SB + 1;
  const int tid = threadIdx.x;
  const int b0 = blockIdx.x * 2;
  const int b1 = b0 + 1;
  const int g = tid >> 6;         // electron group (4 electrons), warp-uniform
  const int ob = (tid & 63) * 4;  // output base (4 outputs)
  const int pg = tid >> 2;        // two-stream pair group
  const int og = (tid & 3) * 8;   // two-stream output base (8 outputs)

  // ---- Phase A: shared small tensors + per-batch x ----
  if (tid < 48) P0->xx[tid] = x[b0 * 48 + tid];
  else if (tid >= 64 && tid < 112) P1->xx[tid - 64] = x[b1 * 48 + tid - 64];
  if (tid < 12) SS->pos[tid] = nuc[tid];
  {
    int q = tid;  // (k*8+i)*4+m, i<8; global (k*16+i)*4+m
    SS->sg[q] = fabsf(sigma[q + (q >> 5) * 32]);
    SS->pw[q] = pi[q + (q >> 5) * 32];
    q = tid + 256;
    SS->sg[q] = fabsf(sigma[q + (q >> 5) * 32]);
    SS->pw[q] = pi[q + (q >> 5) * 32];
  }
  if (tid < 128) SS->eg[tid] = envg[(tid >> 3) * NE + (tid & 7)];
  __syncthreads();

  // ---- Phase B: geometry (both batches) ----
#pragma unroll
  for (int bi = 0; bi < 2; bi++) {
    SmemB* P = bi ? P1 : P0;
    int i = tid >> 4, j = tid & 15;
    float dx = P->xx[j * 3 + 0] - P->xx[i * 3 + 0];
    float dy = P->xx[j * 3 + 1] - P->xx[i * 3 + 1];
    float dz = P->xx[j * 3 + 2] - P->xx[i * 3 + 2];
    float ss = dx * dx + dy * dy + dz * dz;
    float nr = ss > 0.0f ? sqrtf(ss) : 0.0f;
    float* t4 = P->two4 + tid * 5;
    t4[0] = dx; t4[1] = dy; t4[2] = dz; t4[3] = nr;
    if (tid < 64) {
      int n = tid >> 2, m = tid & 3;
      float ex = P->xx[n * 3 + 0] - SS->pos[m * 3 + 0];
      float ey = P->xx[n * 3 + 1] - SS->pos[m * 3 + 1];
      float ez = P->xx[n * 3 + 2] - SS->pos[m * 3 + 2];
      float d = sqrtf(ex * ex + ey * ey + ez * ez);
      float* o1 = P->one + n * 260 + m * 4;
      o1[0] = ex; o1[1] = ey; o1[2] = ez; o1[3] = d;
      P->rr[n * 4 + m] = d;
    }
  }
  __syncthreads();

  // ---- Layer 0 ----
  {
#pragma unroll
    for (int bi = 0; bi < 2; bi++) {
      SmemB* P = bi ? P1 : P0;
      if (tid < 32) {  // g1 means over 16-dim raw one
        int f = tid & 15; bool up = tid < 16;
        float s = 0.0f;
#pragma unroll
        for (int n = 0; n < 8; n++) s += P->one[(up ? n : n + 8) * 260 + f];
        P->g1all[(up ? 0 : 256) + f] = s * 0.125f;
      }
      if (tid < 128) {  // g2 means over 4-dim two4
        int i = tid >> 3, c2 = tid & 7;
        int col = c2 & 3; bool up2 = c2 < 4;
        float s = 0.0f;
#pragma unroll
        for (int j = 0; j < 8; j++) s += P->two4[(i * NE + (up2 ? j : j + 8)) * 5 + col];
        (up2 ? P->g2u : P->g2d)[i * 32 + col] = s * 0.125f;
      }
    }
    // stage two-stream layer-0 weights (shared)
    if (tid < 128) SS->wwt[(tid & 3) * 36 + (tid >> 2)] = __ldg(w0w + tid);
    if (tid < 32) SS->bw[tid] = __ldg(w0b + tid);
    __syncthreads();

    // build f0 vectors [16][60] per batch
#pragma unroll
    for (int bi = 0; bi < 2; bi++) {
      SmemB* P = bi ? P1 : P0;
#pragma unroll
      for (int e = 0; e < 4; e++) {
        int idx = tid + e * TPB;
        if (idx < 960) {
          int n = idx / 60, cc = idx - n * 60;
          float v;
          if (cc < 16)      v = P->one[n * 260 + cc];
          else if (cc < 32) v = P->g1all[cc - 16];
          else if (cc < 48) v = P->g1all[256 + cc - 32];
          else if (cc < 52) v = P->g2u[n * 32 + (cc - 48)];
          else if (cc < 56) v = P->g2d[n * 32 + (cc - 52)];
          else              v = 0.0f;
          P->f0s[idx] = v;
        }
      }
    }

    float accA[16], accB[16];
#pragma unroll
    for (int q = 0; q < 16; q++) { accA[q] = 0.0f; accB[q] = 0.0f; }
    {
      float rg[8];
      ldg0(v0w, 0, rg);
      for (int T = 0; T < 7; T++) {
        float* cur = SS->wt + (T & 1) * 4160;
        sts0(cur, rg);
        __syncthreads();
        if (T + 1 < 7) ldg0(v0w, (T + 1) * 8, rg);
        one_tile_v2<8, 60>(cur, P0->f0s + (g * 4) * 60 + T * 8,
                           P1->f0s + (g * 4) * 60 + T * 8, ob, accA, accB);
      }
    }
    {
      float4 bb = *(const float4*)(v0b + ob);
#pragma unroll
      for (int r = 0; r < 4; r++) {
        int n = g * 4 + r;
        float4 v;
        v.x = ftanh(accA[r * 4 + 0] + bb.x);
        v.y = ftanh(accA[r * 4 + 1] + bb.y);
        v.z = ftanh(accA[r * 4 + 2] + bb.z);
        v.w = ftanh(accA[r * 4 + 3] + bb.w);
        *(float4*)(P0->one + n * 260 + ob) = v;
        v.x = ftanh(accB[r * 4 + 0] + bb.x);
        v.y = ftanh(accB[r * 4 + 1] + bb.y);
        v.z = ftanh(accB[r * 4 + 2] + bb.z);
        v.w = ftanh(accB[r * 4 + 3] + bb.w);
        *(float4*)(P1->one + n * 260 + ob) = v;
      }
    }
    // two-stream layer 0 (K=4), per batch
#pragma unroll
    for (int bi = 0; bi < 2; bi++) {
      SmemB* P = bi ? P1 : P0;
      float acc2[32];
#pragma unroll
      for (int q = 0; q < 32; q++) acc2[q] = 0.0f;
#pragma unroll
      for (int f = 0; f < 4; f++) {
        float4 w0v = *(const float4*)(SS->wwt + f * 36 + og);
        float4 w1v = *(const float4*)(SS->wwt + f * 36 + og + 4);
#pragma unroll
        for (int r = 0; r < 4; r++) {
          float av = P->two4[(r * 64 + pg) * 5 + f];
          acc2[r*8+0] = fmaf(av, w0v.x, acc2[r*8+0]);
          acc2[r*8+1] = fmaf(av, w0v.y, acc2[r*8+1]);
          acc2[r*8+2] = fmaf(av, w0v.z, acc2[r*8+2]);
          acc2[r*8+3] = fmaf(av, w0v.w, acc2[r*8+3]);
          acc2[r*8+4] = fmaf(av, w1v.x, acc2[r*8+4]);
          acc2[r*8+5] = fmaf(av, w1v.y, acc2[r*8+5]);
          acc2[r*8+6] = fmaf(av, w1v.z, acc2[r*8+6]);
          acc2[r*8+7] = fmaf(av, w1v.w, acc2[r*8+7]);
        }
      }
      float4 bb0 = *(const float4*)(SS->bw + og);
      float4 bb1 = *(const float4*)(SS->bw + og + 4);
#pragma unroll
      for (int r = 0; r < 4; r++) {
        float* rowp = P->two + (r * 64 + pg) * 36 + og;
        float4 v0, v1;
        v0.x = ftanh(acc2[r*8+0] + bb0.x); v0.y = ftanh(acc2[r*8+1] + bb0.y);
        v0.z = ftanh(acc2[r*8+2] + bb0.z); v0.w = ftanh(acc2[r*8+3] + bb0.w);
        v1.x = ftanh(acc2[r*8+4] + bb1.x); v1.y = ftanh(acc2[r*8+5] + bb1.y);
        v1.z = ftanh(acc2[r*8+6] + bb1.z); v1.w = ftanh(acc2[r*8+7] + bb1.w);
        *(float4*)(rowp) = v0;
        *(float4*)(rowp + 4) = v1;
      }
    }
  }

  // ---- Layers 1..3 ----
  for (int l = 1; l < 4; l++) {
    __syncthreads();
    const float* Wv = vw + (l - 1) * (256 * 832);
    // g means, per batch
#pragma unroll
    for (int bi = 0; bi < 2; bi++) {
      SmemB* P = bi ? P1 : P0;
      float su = 0.0f, sd = 0.0f;
#pragma unroll
      for (int n = 0; n < 8; n++) {
        su += P->one[n * 260 + tid];
        sd += P->one[(n + 8) * 260 + tid];
      }
      P->g1all[tid] = su * 0.125f;
      P->g1all[256 + tid] = sd * 0.125f;
#pragma unroll
      for (int rep = 0; rep < 2; rep++) {
        int idx = tid + rep * TPB;
        int i = idx >> 5, o = idx & 31;
        float a = 0.0f, bb = 0.0f;
#pragma unroll
        for (int j = 0; j < 8; j++) {
          a  += P->two[(i * NE + j) * 36 + o];
          bb += P->two[(i * NE + j + 8) * 36 + o];
        }
        P->g2u[i * 32 + o] = a * 0.125f;
        P->g2d[i * 32 + o] = bb * 0.125f;
      }
    }
    // stage two-stream weights (shared; barriers below order it)
    {
      const float* Ww = ww + (l - 1) * 1024;
#pragma unroll
      for (int e = 0; e < 4; e++) {
        int idx = tid + e * TPB;
        SS->wwt[(idx & 31) * 36 + (idx >> 5)] = __ldg(Ww + idx);
      }
      if (tid < 32) SS->bw[tid] = __ldg(wb + (l - 1) * 32 + tid);
    }
    __syncthreads();

    // dual c-projection: w row loaded once, dotted with both batches' g1
    {
      int warp = tid >> 5, lane = tid & 31;
      float4 ga0 = *(const float4*)(P0->g1all + 0 * 128 + lane * 4);
      float4 ga1 = *(const float4*)(P0->g1all + 1 * 128 + lane * 4);
      float4 ga2 = *(const float4*)(P0->g1all + 2 * 128 + lane * 4);
      float4 ga3 = *(const float4*)(P0->g1all + 3 * 128 + lane * 4);
      float4 gb0 = *(const float4*)(P1->g1all + 0 * 128 + lane * 4);
      float4 gb1 = *(const float4*)(P1->g1all + 1 * 128 + lane * 4);
      float4 gb2 = *(const float4*)(P1->g1all + 2 * 128 + lane * 4);
      float4 gb3 = *(const float4*)(P1->g1all + 3 * 128 + lane * 4);
#pragma unroll 2
      for (int rr = 0; rr < 32; rr++) {
        int row = warp * 32 + rr;
        const float* wrow = Wv + row * 832 + 256 + lane * 4;
        float4 w0 = __ldg((const float4*)(wrow));
        float4 w1 = __ldg((const float4*)(wrow + 128));
        float4 w2 = __ldg((const float4*)(wrow + 256));
        float4 w3 = __ldg((const float4*)(wrow + 384));
        float sA = w0.x*ga0.x + w0.y*ga0.y + w0.z*ga0.z + w0.w*ga0.w
                 + w1.x*ga1.x + w1.y*ga1.y + w1.z*ga1.z + w1.w*ga1.w
                 + w2.x*ga2.x + w2.y*ga2.y + w2.z*ga2.z + w2.w*ga2.w
                 + w3.x*ga3.x + w3.y*ga3.y + w3.z*ga3.z + w3.w*ga3.w;
        float sB = w0.x*gb0.x + w0.y*gb0.y + w0.z*gb0.z + w0.w*gb0.w
                 + w1.x*gb1.x + w1.y*gb1.y + w1.z*gb1.z + w1.w*gb1.w
                 + w2.x*gb2.x + w2.y*gb2.y + w2.z*gb2.z + w2.w*gb2.w
                 + w3.x*gb3.x + w3.y*gb3.y + w3.z*gb3.z + w3.w*gb3.w;
#pragma unroll
        for (int off = 16; off; off >>= 1) {
          sA += __shfl_xor_sync(0xffffffffu, sA, off);
          sB += __shfl_xor_sync(0xffffffffu, sB, off);
        }
        if (lane == 0) {
          float bv = __ldg(vb + (l - 1) * 256 + row);
          P0->c[row] = sA + bv;
          P1->c[row] = sB + bv;
        }
      }
    }

    // dual electron GEMM: cols 0..255 (one) + 768..831 (g2)
    float accA[16], accB[16];
#pragma unroll
    for (int q = 0; q < 16; q++) { accA[q] = 0.0f; accB[q] = 0.0f; }
    {
      float4 rg[4];
      ldg_t16(Wv, 832, 0, rg);
      for (int T = 0; T < 20; T++) {
        float* cur = SS->wt + (T & 1) * 4160;
        sts_t16(cur, rg);
        __syncthreads();
        int Tn = T + 1;
        if (Tn < 20) {
          int f0 = (Tn < 16) ? Tn * 16 : 768 + (Tn - 16) * 16;
          ldg_t16(Wv, 832, f0, rg);
        }
        if (T < 16) {
          one_tile_v2<16, 260>(cur, P0->one + (g * 4) * 260 + T * 16,
                               P1->one + (g * 4) * 260 + T * 16, ob, accA, accB);
        } else {
          int off2 = (g * 4) * 32 + ((T & 1) ? 16 : 0);
          const float* aA = ((T < 18) ? P0->g2u : P0->g2d) + off2;
          const float* aB = ((T < 18) ? P1->g2u : P1->g2d) + off2;
          one_tile_v2<16, 32>(cur, aA, aB, ob, accA, accB);
        }
      }
    }
    // writeback with residual (c written pre-loop; tile barriers order it)
    {
      float4 cA = *(const float4*)(P0->c + ob);
      float4 cB = *(const float4*)(P1->c + ob);
#pragma unroll
      for (int r = 0; r < 4; r++) {
        int n = g * 4 + r;
        float4 old = *(const float4*)(P0->one + n * 260 + ob);
        float4 v;
        v.x = ftanh(accA[r * 4 + 0] + cA.x) + old.x;
        v.y = ftanh(accA[r * 4 + 1] + cA.y) + old.y;
        v.z = ftanh(accA[r * 4 + 2] + cA.z) + old.z;
        v.w = ftanh(accA[r * 4 + 3] + cA.w) + old.w;
        *(float4*)(P0->one + n * 260 + ob) = v;
        old = *(const float4*)(P1->one + n * 260 + ob);
        v.x = ftanh(accB[r * 4 + 0] + cB.x) + old.x;
        v.y = ftanh(accB[r * 4 + 1] + cB.y) + old.y;
        v.z = ftanh(accB[r * 4 + 2] + cB.z) + old.z;
        v.w = ftanh(accB[r * 4 + 3] + cB.w) + old.w;
        *(float4*)(P1->one + n * 260 + ob) = v;
      }
    }
    // two-stream GEMM (K=32) + residual, per batch
#pragma unroll
    for (int bi = 0; bi < 2; bi++) {
      SmemB* P = bi ? P1 : P0;
      float acc2[32];
#pragma unroll
      for (int q = 0; q < 32; q++) acc2[q] = 0.0f;
#pragma unroll
      for (int f4 = 0; f4 < 8; f4++) {
        float4 a0 = *(const float4*)(P->two + (0 * 64 + pg) * 36 + f4 * 4);
        float4 a1 = *(const float4*)(P->two + (1 * 64 + pg) * 36 + f4 * 4);
        float4 a2 = *(const float4*)(P->two + (2 * 64 + pg) * 36 + f4 * 4);
        float4 a3 = *(const float4*)(P->two + (3 * 64 + pg) * 36 + f4 * 4);
#pragma unroll
        for (int k = 0; k < 4; k++) {
          int f = f4 * 4 + k;
          float4 wA = *(const float4*)(SS->wwt + f * 36 + og);
          float4 wB = *(const float4*)(SS->wwt + f * 36 + og + 4);
          float v0 = (k == 0) ? a0.x : (k == 1) ? a0.y : (k == 2) ? a0.z : a0.w;
          float v1 = (k == 0) ? a1.x : (k == 1) ? a1.y : (k == 2) ? a1.z : a1.w;
          float v2 = (k == 0) ? a2.x : (k == 1) ? a2.y : (k == 2) ? a2.z : a2.w;
          float v3 = (k == 0) ? a3.x : (k == 1) ? a3.y : (k == 2) ? a3.z : a3.w;
#define TWO_FMA(RR, AV) \
          acc2[(RR)*8+0] = fmaf(AV, wA.x, acc2[(RR)*8+0]); \
          acc2[(RR)*8+1] = fmaf(AV, wA.y, acc2[(RR)*8+1]); \
          acc2[(RR)*8+2] = fmaf(AV, wA.z, acc2[(RR)*8+2]); \
          acc2[(RR)*8+3] = fmaf(AV, wA.w, acc2[(RR)*8+3]); \
          acc2[(RR)*8+4] = fmaf(AV, wB.x, acc2[(RR)*8+4]); \
          acc2[(RR)*8+5] = fmaf(AV, wB.y, acc2[(RR)*8+5]); \
          acc2[(RR)*8+6] = fmaf(AV, wB.z, acc2[(RR)*8+6]); \
          acc2[(RR)*8+7] = fmaf(AV, wB.w, acc2[(RR)*8+7]);
          TWO_FMA(0, v0) TWO_FMA(1, v1) TWO_FMA(2, v2) TWO_FMA(3, v3)
#undef TWO_FMA
        }
      }
      // row-sharing threads (same pg) are warp-local: finish reads before writeback
      __syncwarp();
      float4 bb0 = *(const float4*)(SS->bw + og);
      float4 bb1 = *(const float4*)(SS->bw + og + 4);
#pragma unroll
      for (int r = 0; r < 4; r++) {
        float* rowp = P->two + (r * 64 + pg) * 36 + og;
        float4 o0 = *(const float4*)(rowp);
        float4 o1 = *(const float4*)(rowp + 4);
        o0.x = ftanh(acc2[r*8+0] + bb0.x) + o0.x;
        o0.y = ftanh(acc2[r*8+1] + bb0.y) + o0.y;
        o0.z = ftanh(acc2[r*8+2] + bb0.z) + o0.z;
        o0.w = ftanh(acc2[r*8+3] + bb0.w) + o0.w;
        o1.x = ftanh(acc2[r*8+4] + bb1.x) + o1.x;
        o1.y = ftanh(acc2[r*8+5] + bb1.y) + o1.y;
        o1.z = ftanh(acc2[r*8+6] + bb1.z) + o1.z;
        o1.w = ftanh(acc2[r*8+7] + bb1.w) + o1.w;
        *(float4*)(rowp) = o0;
        *(float4*)(rowp + 4) = o1;
      }
      __syncwarp();
    }
  }

  __syncthreads();

  // ---- Envelope / orbitals (dual: env_w float4 loaded once) ----
  {
    int k = tid >> 4, i = (tid >> 1) & 7, jh = tid & 1;
    const float* wrow = envw + (k * 16 + i) * 256;
    float aA[8], aB[8];
#pragma unroll
    for (int j = 0; j < 8; j++) { aA[j] = 0.0f; aB[j] = 0.0f; }
    for (int f4 = 0; f4 < 64; f4++) {
      float4 w = __ldg((const float4*)(wrow + f4 * 4));
#pragma unroll
      for (int j = 0; j < 8; j++) {
        float4 a = *(const float4*)(P0->one + (jh * 8 + j) * 260 + f4 * 4);
        aA[j] += w.x * a.x + w.y * a.y + w.z * a.z + w.w * a.w;
        a = *(const float4*)(P1->one + (jh * 8 + j) * 260 + f4 * 4);
        aB[j] += w.x * a.x + w.y * a.y + w.z * a.z + w.w * a.w;
      }
    }
    float lg = 256.0f * SS->eg[k * 8 + i];
    int si = (k * 8 + i) * 4;
    float p0 = SS->pw[si], p1 = SS->pw[si + 1], p2 = SS->pw[si + 2], p3 = SS->pw[si + 3];
    float s0 = SS->sg[si], s1 = SS->sg[si + 1], s2 = SS->sg[si + 2], s3 = SS->sg[si + 3];
#pragma unroll
    for (int j = 0; j < 8; j++) {
      int col = jh * 8 + j;
      const float* rA = P0->rr + col * 4;
      const float* rB = P1->rr + col * 4;
      float envA = p0 * __expf(-s0 * rA[0]) + p1 * __expf(-s1 * rA[1]) +
                   p2 * __expf(-s2 * rA[2]) + p3 * __expf(-s3 * rA[3]);
      float envB = p0 * __expf(-s0 * rB[0]) + p1 * __expf(-s1 * rB[1]) +
                   p2 * __expf(-s2 * rB[2]) + p3 * __expf(-s3 * rB[3]);
      P0->two4[(jh * 16 + k) * 65 + i * 8 + j] = (aA[j] + lg) * envA;
      P1->two4[(jh * 16 + k) * 65 + i * 8 + j] = (aB[j] + lg) * envB;
    }
  }
  __syncthreads();

  // ---- Determinants: 64 matrices 8x8 (32 per batch), pivoted LU ----
  if (tid < 64) {
    SmemB* P = (tid < 32) ? P0 : P1;
    int q = tid & 31;
    float* D = P->two4;
    float* A = D + q * 65;
    float dv = 1.0f;
    for (int cph = 0; cph < 8; cph++) {
      int p = cph; float mx = fabsf(A[cph * 8 + cph]);
      for (int r = cph + 1; r < 8; r++) {
        float fv = fabsf(A[r * 8 + cph]);
        if (fv > mx) { mx = fv; p = r; }
      }
      if (mx == 0.0f) { dv = 0.0f; break; }
      if (p != cph) {
#pragma unroll
        for (int cc = 0; cc < 8; cc++) {
          float t = A[cph * 8 + cc]; A[cph * 8 + cc] = A[p * 8 + cc]; A[p * 8 + cc] = t;
        }
        dv = -dv;
      }
      float piv = A[cph * 8 + cph];
      dv *= piv;
      float inv = 1.0f / piv;
      for (int r = cph + 1; r < 8; r++) {
        float m = A[r * 8 + cph] * inv;
        for (int cc = cph + 1; cc < 8; cc++) A[r * 8 + cc] -= m * A[cph * 8 + cc];
      }
    }
    (D + 2080)[q] = dv;
  }
  __syncthreads();
  if (tid < 16) {
    float* D = P0->two4;
    (D + 2112)[tid] = (D + 2080)[tid] * (D + 2080)[16 + tid];
  } else if (tid >= 128 && tid < 144) {
    float* D = P1->two4;
    (D + 2112)[tid - 128] = (D + 2080)[tid - 128] * (D + 2080)[16 + tid - 128];
  }
  __syncthreads();
  if (tid == 0) {
    float s = 0.0f;
#pragma unroll
    for (int k = 0; k < 16; k++) s += (P0->two4 + 2112)[k];
    out[b0] = s;
  } else if (tid == 128) {
    float s = 0.0f;
#pragma unroll
    for (int k = 0; k < 16; k++) s += (P1->two4 + 2112)[k];
    out[b1] = s;
  }
}

}  // namespace FN

extern "C" void kernel_launch(void* const* d_in, const int* in_sizes, int n_in,
                              void* d_out, int out_size) {
  const float* x    = (const float*)d_in[0];
  const float* nuc  = (const float*)d_in[1];
  const float* v0w  = (const float*)d_in[2];
  const float* v0b  = (const float*)d_in[3];
  const float* vw   = (const float*)d_in[4];
  const float* vb   = (const float*)d_in[5];
  const float* w0w  = (const float*)d_in[6];
  const float* w0b  = (const float*)d_in[7];
  const float* ww   = (const float*)d_in[8];
  const float* wb   = (const float*)d_in[9];
  const float* envw = (const float*)d_in[10];
  const float* envg = (const float*)d_in[11];
  const float* sig  = (const float*)d_in[12];
  const float* pi   = (const float*)d_in[13];
  float* out = (float*)d_out;

  int B = in_sizes[0] / 48;
  int smem = (int)(sizeof(FN::SmemS) + 2 * sizeof(FN::SmemB));
  cudaFuncSetAttribute(FN::ferminet_kernel, cudaFuncAttributeMaxDynamicSharedMemorySize, smem);
  FN::ferminet_kernel<<<B / 2, TPB, smem>>>(x, nuc, v0w, v0b, vw, vb, w0w, w0b, ww, wb,
                                            envw, envg, sig, pi, out);
}

// round 14
// speedup vs baseline: 2.2574x; 1.1267x over previous
#include <cuda_runtime.h>
#include <math.h>

#define TPB 512
#define HALF 256

namespace FN {

constexpr int NE = 16;

// per-batch arena
struct __align__(16) SmemB {
  float one[NE * 260];   // one-stream activations
  float two[256 * 36];   // two-stream activations, row (i*16+j)
  float two4[256 * 5];   // layer-0 two features } det arena alias (2240 floats)
  float f0s[16 * 60];    // layer-0 f vectors    }
  float g1all[512];      // [0:256)=g1u, [256:512)=g1d
  float g2u[512], g2d[512];
  float c[256];
  float xx[48], rr[64];
};
// shared arena
struct __align__(16) SmemS {
  float wt[2 * 16 * 260];  // double-buffered weight tiles, transposed [fi][o]
  float wwt[32 * 36];      // two-stream weights transposed [f][o]
  float bw[32];
  float pos[16];
  float sg[512], pw[512], eg[128];
};

#define BARS(ID, CNT) asm volatile("bar.sync %0, %1;" :: "r"(ID), "r"(CNT) : "memory")
#define BARA(ID, CNT) asm volatile("bar.arrive %0, %1;" :: "r"(ID), "r"(CNT) : "memory")

__device__ __forceinline__ float ftanh(float x) {
  float ax = fabsf(x);
  float e = __expf(-2.0f * ax);
  float t = __fdividef(1.0f - e, 1.0f + e);
  return x >= 0.0f ? t : -t;
}

// ---- staging helpers (GEMM half: 256 threads, pass th) ----
__device__ __forceinline__ void ldg_t16(const float* __restrict__ W, int ldw, int f0,
                                        float4* rg, int th) {
#pragma unroll
  for (int e = 0; e < 4; e++) {
    int j = th + e * HALF;
    int o = j >> 2, fq = j & 3;
    rg[e] = __ldg((const float4*)(W + o * ldw + f0 + fq * 4));
  }
}
__device__ __forceinline__ void sts_t16(float* buf, const float4* rg, int th) {
#pragma unroll
  for (int e = 0; e < 4; e++) {
    int j = th + e * HALF;
    int o = j >> 2, fq = j & 3;
    buf[(fq * 4 + 0) * 260 + o] = rg[e].x;
    buf[(fq * 4 + 1) * 260 + o] = rg[e].y;
    buf[(fq * 4 + 2) * 260 + o] = rg[e].z;
    buf[(fq * 4 + 3) * 260 + o] = rg[e].w;
  }
}
__device__ __forceinline__ void ldg0(const float* __restrict__ W, int f0, float* rg, int th) {
#pragma unroll
  for (int e = 0; e < 8; e++) {
    int idx = th + e * HALF;
    int o = idx >> 3, fi = idx & 7;
    int col = f0 + fi;
    rg[e] = (col < 56) ? __ldg(W + o * 56 + col) : 0.0f;
  }
}
__device__ __forceinline__ void sts0(float* buf, const float* rg, int th) {
#pragma unroll
  for (int e = 0; e < 8; e++) {
    int idx = th + e * HALF;
    int o = idx >> 3, fi = idx & 7;
    buf[fi * 260 + o] = rg[e];
  }
}

#define RF(ACC, RR, AV) do { \
  ACC[(RR)*4+0] = fmaf(AV.x, w0.x, ACC[(RR)*4+0]); \
  ACC[(RR)*4+1] = fmaf(AV.x, w0.y, ACC[(RR)*4+1]); \
  ACC[(RR)*4+2] = fmaf(AV.x, w0.z, ACC[(RR)*4+2]); \
  ACC[(RR)*4+3] = fmaf(AV.x, w0.w, ACC[(RR)*4+3]); \
  ACC[(RR)*4+0] = fmaf(AV.y, w1.x, ACC[(RR)*4+0]); \
  ACC[(RR)*4+1] = fmaf(AV.y, w1.y, ACC[(RR)*4+1]); \
  ACC[(RR)*4+2] = fmaf(AV.y, w1.z, ACC[(RR)*4+2]); \
  ACC[(RR)*4+3] = fmaf(AV.y, w1.w, ACC[(RR)*4+3]); \
  ACC[(RR)*4+0] = fmaf(AV.z, w2.x, ACC[(RR)*4+0]); \
  ACC[(RR)*4+1] = fmaf(AV.z, w2.y, ACC[(RR)*4+1]); \
  ACC[(RR)*4+2] = fmaf(AV.z, w2.z, ACC[(RR)*4+2]); \
  ACC[(RR)*4+3] = fmaf(AV.z, w2.w, ACC[(RR)*4+3]); \
  ACC[(RR)*4+0] = fmaf(AV.w, w3.x, ACC[(RR)*4+0]); \
  ACC[(RR)*4+1] = fmaf(AV.w, w3.y, ACC[(RR)*4+1]); \
  ACC[(RR)*4+2] = fmaf(AV.w, w3.z, ACC[(RR)*4+2]); \
  ACC[(RR)*4+3] = fmaf(AV.w, w3.w, ACC[(RR)*4+3]); \
} while (0)

template<int KT, int AS>
__device__ __forceinline__ void one_tile_v2(const float* buf,
                                            const float* actA, const float* actB,
                                            int ob, float* accA, float* accB) {
#pragma unroll
  for (int q = 0; q < KT / 4; q++) {
    float4 w0 = *(const float4*)(buf + (q * 4 + 0) * 260 + ob);
    float4 w1 = *(const float4*)(buf + (q * 4 + 1) * 260 + ob);
    float4 w2 = *(const float4*)(buf + (q * 4 + 2) * 260 + ob);
    float4 w3 = *(const float4*)(buf + (q * 4 + 3) * 260 + ob);
    {
      float4 a0 = *(const float4*)(actA + 0 * AS + q * 4);
      float4 a1 = *(const float4*)(actA + 1 * AS + q * 4);
      float4 a2 = *(const float4*)(actA + 2 * AS + q * 4);
      float4 a3 = *(const float4*)(actA + 3 * AS + q * 4);
      RF(accA, 0, a0); RF(accA, 1, a1); RF(accA, 2, a2); RF(accA, 3, a3);
    }
    {
      float4 a0 = *(const float4*)(actB + 0 * AS + q * 4);
      float4 a1 = *(const float4*)(actB + 1 * AS + q * 4);
      float4 a2 = *(const float4*)(actB + 2 * AS + q * 4);
      float4 a3 = *(const float4*)(actB + 3 * AS + q * 4);
      RF(accB, 0, a0); RF(accB, 1, a1); RF(accB, 2, a2); RF(accB, 3, a3);
    }
  }
}

__global__ void __launch_bounds__(TPB, 1)
ferminet_kernel(const float* __restrict__ x, const float* __restrict__ nuc,
                const float* __restrict__ v0w, const float* __restrict__ v0b,
                const float* __restrict__ vw,  const float* __restrict__ vb,
                const float* __restrict__ w0w, const float* __restrict__ w0b,
                const float* __restrict__ ww,  const float* __restrict__ wb,
                const float* __restrict__ envw, const float* __restrict__ envg,
                const float* __restrict__ sigma, const float* __restrict__ pi,
                float* __restrict__ out) {
  extern __shared__ float smem_raw[];
  SmemS* SS = (SmemS*)smem_raw;
  SmemB* P0 = (SmemB*)(smem_raw + sizeof(SmemS) / 4);
  SmemB* P1 = P0 + 1;
  const int tid = threadIdx.x;
  const int half = tid >> 8;       // 0 = GEMM warps, 1 = AUX warps
  const int th = tid & 255;
  const int b0 = blockIdx.x * 2;
  const int b1 = b0 + 1;
  const int g = th >> 6;           // electron group (GEMM)
  const int ob = (th & 63) * 4;    // output base (GEMM)
  const int pg = th >> 2;          // two-stream pair group (AUX)
  const int og = (th & 3) * 8;     // two-stream output base (AUX)

  // ---- Phase A: smalls (all 512) ----
  if (tid < 48) P0->xx[tid] = x[b0 * 48 + tid];
  else if (tid >= 64 && tid < 112) P1->xx[tid - 64] = x[b1 * 48 + tid - 64];
  if (tid < 12) SS->pos[tid] = nuc[tid];
  {
    int q = tid;  // (k*8+i)*4+m, i<8; global = q + (q>>5)*32
    SS->sg[q] = fabsf(sigma[q + (q >> 5) * 32]);
    SS->pw[q] = pi[q + (q >> 5) * 32];
  }
  if (tid < 128) SS->eg[tid] = envg[(tid >> 3) * NE + (tid & 7)];
  __syncthreads();

  // ---- Phase B: geometry (each half does its own batch) ----
  {
    SmemB* P = half ? P1 : P0;
    int i = th >> 4, j = th & 15;
    float dx = P->xx[j * 3 + 0] - P->xx[i * 3 + 0];
    float dy = P->xx[j * 3 + 1] - P->xx[i * 3 + 1];
    float dz = P->xx[j * 3 + 2] - P->xx[i * 3 + 2];
    float ss = dx * dx + dy * dy + dz * dz;
    float nr = ss > 0.0f ? sqrtf(ss) : 0.0f;
    float* t4 = P->two4 + th * 5;
    t4[0] = dx; t4[1] = dy; t4[2] = dz; t4[3] = nr;
    if (th < 64) {
      int n = th >> 2, m = th & 3;
      float ex = P->xx[n * 3 + 0] - SS->pos[m * 3 + 0];
      float ey = P->xx[n * 3 + 1] - SS->pos[m * 3 + 1];
      float ez = P->xx[n * 3 + 2] - SS->pos[m * 3 + 2];
      float d = sqrtf(ex * ex + ey * ey + ez * ez);
      float* o1 = P->one + n * 260 + m * 4;
      o1[0] = ex; o1[1] = ey; o1[2] = ez; o1[3] = d;
      P->rr[n * 4 + m] = d;
    }
  }
  __syncthreads();

  // ======================= DIVERGENT REGION (named barriers only) =====================
  if (half == 0) {
    // ============== GEMM half ==============
    // ---- Layer 0 ----
    {
      float rg[8];
      ldg0(v0w, 0, rg, th);
      float accA[16], accB[16];
#pragma unroll
      for (int q = 0; q < 16; q++) { accA[q] = 0.0f; accB[q] = 0.0f; }
      BARS(3, 512);  // f0s ready
      for (int T = 0; T < 7; T++) {
        float* cur = SS->wt + (T & 1) * 4160;
        sts0(cur, rg, th);
        BARS(4, HALF);
        if (T + 1 < 7) ldg0(v0w, (T + 1) * 8, rg, th);
        one_tile_v2<8, 60>(cur, P0->f0s + (g * 4) * 60 + T * 8,
                           P1->f0s + (g * 4) * 60 + T * 8, ob, accA, accB);
      }
      float4 bb = *(const float4*)(v0b + ob);
#pragma unroll
      for (int r = 0; r < 4; r++) {
        int n = g * 4 + r;
        float4 v;
        v.x = ftanh(accA[r * 4 + 0] + bb.x); v.y = ftanh(accA[r * 4 + 1] + bb.y);
        v.z = ftanh(accA[r * 4 + 2] + bb.z); v.w = ftanh(accA[r * 4 + 3] + bb.w);
        *(float4*)(P0->one + n * 260 + ob) = v;
        v.x = ftanh(accB[r * 4 + 0] + bb.x); v.y = ftanh(accB[r * 4 + 1] + bb.y);
        v.z = ftanh(accB[r * 4 + 2] + bb.z); v.w = ftanh(accB[r * 4 + 3] + bb.w);
        *(float4*)(P1->one + n * 260 + ob) = v;
      }
      __threadfence_block();
      BARA(5, 512);  // ONE done
    }
    // ---- Layers 1..3 ----
    for (int l = 1; l < 4; l++) {
      const float* Wv = vw + (l - 1) * (256 * 832);
      float4 rg[4];
      ldg_t16(Wv, 832, 0, rg, th);
      float accA[16], accB[16];
#pragma unroll
      for (int q = 0; q < 16; q++) { accA[q] = 0.0f; accB[q] = 0.0f; }
      for (int T = 0; T < 20; T++) {
        float* cur = SS->wt + (T & 1) * 4160;
        sts_t16(cur, rg, th);
        BARS(4, HALF);
        if (T == 16) BARS(1, 512);  // g2u/g2d ready (aux)
        int Tn = T + 1;
        if (Tn < 20) {
          int f0 = (Tn < 16) ? Tn * 16 : 768 + (Tn - 16) * 16;
          ldg_t16(Wv, 832, f0, rg, th);
        }
        if (T < 16) {
          one_tile_v2<16, 260>(cur, P0->one + (g * 4) * 260 + T * 16,
                               P1->one + (g * 4) * 260 + T * 16, ob, accA, accB);
        } else {
          int off2 = (g * 4) * 32 + ((T & 1) ? 16 : 0);
          const float* aA = ((T < 18) ? P0->g2u : P0->g2d) + off2;
          const float* aB = ((T < 18) ? P1->g2u : P1->g2d) + off2;
          one_tile_v2<16, 32>(cur, aA, aB, ob, accA, accB);
        }
      }
      BARS(6, 512);  // c ready (aux)
      {
        float4 cA = *(const float4*)(P0->c + ob);
        float4 cB = *(const float4*)(P1->c + ob);
#pragma unroll
        for (int r = 0; r < 4; r++) {
          int n = g * 4 + r;
          float4 old = *(const float4*)(P0->one + n * 260 + ob);
          float4 v;
          v.x = ftanh(accA[r * 4 + 0] + cA.x) + old.x;
          v.y = ftanh(accA[r * 4 + 1] + cA.y) + old.y;
          v.z = ftanh(accA[r * 4 + 2] + cA.z) + old.z;
          v.w = ftanh(accA[r * 4 + 3] + cA.w) + old.w;
          *(float4*)(P0->one + n * 260 + ob) = v;
          old = *(const float4*)(P1->one + n * 260 + ob);
          v.x = ftanh(accB[r * 4 + 0] + cB.x) + old.x;
          v.y = ftanh(accB[r * 4 + 1] + cB.y) + old.y;
          v.z = ftanh(accB[r * 4 + 2] + cB.z) + old.z;
          v.w = ftanh(accB[r * 4 + 3] + cB.w) + old.w;
          *(float4*)(P1->one + n * 260 + ob) = v;
        }
      }
      __threadfence_block();
      if (l < 3) BARA(5, 512);
    }
  } else {
    // ============== AUX half ==============
    // ---- Layer 0 ----
    {
#pragma unroll
      for (int bi = 0; bi < 2; bi++) {
        SmemB* P = bi ? P1 : P0;
        if (th < 32) {  // g1 means over 16-dim raw one
          int f = th & 15; bool up = th < 16;
          float s = 0.0f;
#pragma unroll
          for (int n = 0; n < 8; n++) s += P->one[(up ? n : n + 8) * 260 + f];
          P->g1all[(up ? 0 : 256) + f] = s * 0.125f;
        }
        if (th < 128) {  // g2 means over 4-dim two4
          int i = th >> 3, c2 = th & 7;
          int col = c2 & 3; bool up2 = c2 < 4;
          float s = 0.0f;
#pragma unroll
          for (int j = 0; j < 8; j++) s += P->two4[(i * NE + (up2 ? j : j + 8)) * 5 + col];
          (up2 ? P->g2u : P->g2d)[i * 32 + col] = s * 0.125f;
        }
      }
      if (th < 128) SS->wwt[(th & 3) * 36 + (th >> 2)] = __ldg(w0w + th);
      if (th < 32) SS->bw[th] = __ldg(w0b + th);
      BARS(2, HALF);  // aux-internal: means + wwt visible
      // build f0s [16][60] per batch
#pragma unroll
      for (int bi = 0; bi < 2; bi++) {
        SmemB* P = bi ? P1 : P0;
#pragma unroll
        for (int e = 0; e < 4; e++) {
          int idx = th + e * HALF;
          if (idx < 960) {
            int n = idx / 60, cc = idx - n * 60;
            float v;
            if (cc < 16)      v = P->one[n * 260 + cc];
            else if (cc < 32) v = P->g1all[cc - 16];
            else if (cc < 48) v = P->g1all[256 + cc - 32];
            else if (cc < 52) v = P->g2u[n * 32 + (cc - 48)];
            else if (cc < 56) v = P->g2d[n * 32 + (cc - 52)];
            else              v = 0.0f;
            P->f0s[idx] = v;
          }
        }
      }
      __threadfence_block();
      BARA(3, 512);  // f0s published to gemm
      // two-stream layer 0 (K=4), both batches
#pragma unroll
      for (int bi = 0; bi < 2; bi++) {
        SmemB* P = bi ? P1 : P0;
        float acc2[32];
#pragma unroll
        for (int q = 0; q < 32; q++) acc2[q] = 0.0f;
#pragma unroll
        for (int f = 0; f < 4; f++) {
          float4 w0v = *(const float4*)(SS->wwt + f * 36 + og);
          float4 w1v = *(const float4*)(SS->wwt + f * 36 + og + 4);
#pragma unroll
          for (int r = 0; r < 4; r++) {
            float av = P->two4[(r * 64 + pg) * 5 + f];
            acc2[r*8+0] = fmaf(av, w0v.x, acc2[r*8+0]);
            acc2[r*8+1] = fmaf(av, w0v.y, acc2[r*8+1]);
            acc2[r*8+2] = fmaf(av, w0v.z, acc2[r*8+2]);
            acc2[r*8+3] = fmaf(av, w0v.w, acc2[r*8+3]);
            acc2[r*8+4] = fmaf(av, w1v.x, acc2[r*8+4]);
            acc2[r*8+5] = fmaf(av, w1v.y, acc2[r*8+5]);
            acc2[r*8+6] = fmaf(av, w1v.z, acc2[r*8+6]);
            acc2[r*8+7] = fmaf(av, w1v.w, acc2[r*8+7]);
          }
        }
        float4 bb0 = *(const float4*)(SS->bw + og);
        float4 bb1 = *(const float4*)(SS->bw + og + 4);
#pragma unroll
        for (int r = 0; r < 4; r++) {
          float* rowp = P->two + (r * 64 + pg) * 36 + og;
          float4 v0, v1;
          v0.x = ftanh(acc2[r*8+0] + bb0.x); v0.y = ftanh(acc2[r*8+1] + bb0.y);
          v0.z = ftanh(acc2[r*8+2] + bb0.z); v0.w = ftanh(acc2[r*8+3] + bb0.w);
          v1.x = ftanh(acc2[r*8+4] + bb1.x); v1.y = ftanh(acc2[r*8+5] + bb1.y);
          v1.z = ftanh(acc2[r*8+6] + bb1.z); v1.w = ftanh(acc2[r*8+7] + bb1.w);
          *(float4*)(rowp) = v0;
          *(float4*)(rowp + 4) = v1;
        }
      }
    }
    // ---- Layers 1..3 ----
    for (int l = 1; l < 4; l++) {
      const float* Wv = vw + (l - 1) * (256 * 832);
      BARS(5, 512);  // one ready (gemm, prev layer)
      // g means, both batches
#pragma unroll
      for (int bi = 0; bi < 2; bi++) {
        SmemB* P = bi ? P1 : P0;
        float su = 0.0f, sd = 0.0f;
#pragma unroll
        for (int n = 0; n < 8; n++) {
          su += P->one[n * 260 + th];
          sd += P->one[(n + 8) * 260 + th];
        }
        P->g1all[th] = su * 0.125f;
        P->g1all[256 + th] = sd * 0.125f;
#pragma unroll
        for (int rep = 0; rep < 2; rep++) {
          int idx = th + rep * HALF;
          int i = idx >> 5, o = idx & 31;
          float a = 0.0f, bb = 0.0f;
#pragma unroll
          for (int j = 0; j < 8; j++) {
            a  += P->two[(i * NE + j) * 36 + o];
            bb += P->two[(i * NE + j + 8) * 36 + o];
          }
          P->g2u[i * 32 + o] = a * 0.125f;
          P->g2d[i * 32 + o] = bb * 0.125f;
        }
      }
      // stage this layer's two-stream weights
      {
        const float* Ww = ww + (l - 1) * 1024;
#pragma unroll
        for (int e = 0; e < 4; e++) {
          int idx = th + e * HALF;
          SS->wwt[(idx & 31) * 36 + (idx >> 5)] = __ldg(Ww + idx);
        }
        if (th < 32) SS->bw[th] = __ldg(wb + (l - 1) * 32 + th);
      }
      BARS(2, HALF);          // aux-internal: means + wwt visible
      __threadfence_block();
      BARA(1, 512);           // publish g2 to gemm
      // dual c-projection
      {
        int warp = th >> 5, lane = th & 31;
        float4 ga0 = *(const float4*)(P0->g1all + 0 * 128 + lane * 4);
        float4 ga1 = *(const float4*)(P0->g1all + 1 * 128 + lane * 4);
        float4 ga2 = *(const float4*)(P0->g1all + 2 * 128 + lane * 4);
        float4 ga3 = *(const float4*)(P0->g1all + 3 * 128 + lane * 4);
        float4 gb0 = *(const float4*)(P1->g1all + 0 * 128 + lane * 4);
        float4 gb1 = *(const float4*)(P1->g1all + 1 * 128 + lane * 4);
        float4 gb2 = *(const float4*)(P1->g1all + 2 * 128 + lane * 4);
        float4 gb3 = *(const float4*)(P1->g1all + 3 * 128 + lane * 4);
#pragma unroll 2
        for (int rr = 0; rr < 32; rr++) {
          int row = warp * 32 + rr;
          const float* wrow = Wv + row * 832 + 256 + lane * 4;
          float4 w0 = __ldg((const float4*)(wrow));
          float4 w1 = __ldg((const float4*)(wrow + 128));
          float4 w2 = __ldg((const float4*)(wrow + 256));
          float4 w3 = __ldg((const float4*)(wrow + 384));
          float sA = w0.x*ga0.x + w0.y*ga0.y + w0.z*ga0.z + w0.w*ga0.w
                   + w1.x*ga1.x + w1.y*ga1.y + w1.z*ga1.z + w1.w*ga1.w
                   + w2.x*ga2.x + w2.y*ga2.y + w2.z*ga2.z + w2.w*ga2.w
                   + w3.x*ga3.x + w3.y*ga3.y + w3.z*ga3.z + w3.w*ga3.w;
          float sB = w0.x*gb0.x + w0.y*gb0.y + w0.z*gb0.z + w0.w*gb0.w
                   + w1.x*gb1.x + w1.y*gb1.y + w1.z*gb1.z + w1.w*gb1.w
                   + w2.x*gb2.x + w2.y*gb2.y + w2.z*gb2.z + w2.w*gb2.w
                   + w3.x*gb3.x + w3.y*gb3.y + w3.z*gb3.z + w3.w*gb3.w;
#pragma unroll
          for (int off = 16; off; off >>= 1) {
            sA += __shfl_xor_sync(0xffffffffu, sA, off);
            sB += __shfl_xor_sync(0xffffffffu, sB, off);
          }
          if (lane == 0) {
            float bv = __ldg(vb + (l - 1) * 256 + row);
            P0->c[row] = sA + bv;
            P1->c[row] = sB + bv;
          }
        }
      }
      __threadfence_block();
      BARA(6, 512);  // publish c to gemm
      // two-stream GEMM (K=32) + residual, both batches
#pragma unroll
      for (int bi = 0; bi < 2; bi++) {
        SmemB* P = bi ? P1 : P0;
        float acc2[32];
#pragma unroll
        for (int q = 0; q < 32; q++) acc2[q] = 0.0f;
#pragma unroll
        for (int f4 = 0; f4 < 8; f4++) {
          float4 a0 = *(const float4*)(P->two + (0 * 64 + pg) * 36 + f4 * 4);
          float4 a1 = *(const float4*)(P->two + (1 * 64 + pg) * 36 + f4 * 4);
          float4 a2 = *(const float4*)(P->two + (2 * 64 + pg) * 36 + f4 * 4);
          float4 a3 = *(const float4*)(P->two + (3 * 64 + pg) * 36 + f4 * 4);
#pragma unroll
          for (int k = 0; k < 4; k++) {
            int f = f4 * 4 + k;
            float4 wA = *(const float4*)(SS->wwt + f * 36 + og);
            float4 wB = *(const float4*)(SS->wwt + f * 36 + og + 4);
            float v0 = (k == 0) ? a0.x : (k == 1) ? a0.y : (k == 2) ? a0.z : a0.w;
            float v1 = (k == 0) ? a1.x : (k == 1) ? a1.y : (k == 2) ? a1.z : a1.w;
            float v2 = (k == 0) ? a2.x : (k == 1) ? a2.y : (k == 2) ? a2.z : a2.w;
            float v3 = (k == 0) ? a3.x : (k == 1) ? a3.y : (k == 2) ? a3.z : a3.w;
#define TWO_FMA(RR, AV) \
            acc2[(RR)*8+0] = fmaf(AV, wA.x, acc2[(RR)*8+0]); \
            acc2[(RR)*8+1] = fmaf(AV, wA.y, acc2[(RR)*8+1]); \
            acc2[(RR)*8+2] = fmaf(AV, wA.z, acc2[(RR)*8+2]); \
            acc2[(RR)*8+3] = fmaf(AV, wA.w, acc2[(RR)*8+3]); \
            acc2[(RR)*8+4] = fmaf(AV, wB.x, acc2[(RR)*8+4]); \
            acc2[(RR)*8+5] = fmaf(AV, wB.y, acc2[(RR)*8+5]); \
            acc2[(RR)*8+6] = fmaf(AV, wB.z, acc2[(RR)*8+6]); \
            acc2[(RR)*8+7] = fmaf(AV, wB.w, acc2[(RR)*8+7]);
            TWO_FMA(0, v0) TWO_FMA(1, v1) TWO_FMA(2, v2) TWO_FMA(3, v3)
#undef TWO_FMA
          }
        }
        __syncwarp();  // row-sharing threads are warp-local
        float4 bb0 = *(const float4*)(SS->bw + og);
        float4 bb1 = *(const float4*)(SS->bw + og + 4);
#pragma unroll
        for (int r = 0; r < 4; r++) {
          float* rowp = P->two + (r * 64 + pg) * 36 + og;
          float4 o0 = *(const float4*)(rowp);
          float4 o1 = *(const float4*)(rowp + 4);
          o0.x = ftanh(acc2[r*8+0] + bb0.x) + o0.x;
          o0.y = ftanh(acc2[r*8+1] + bb0.y) + o0.y;
          o0.z = ftanh(acc2[r*8+2] + bb0.z) + o0.z;
          o0.w = ftanh(acc2[r*8+3] + bb0.w) + o0.w;
          o1.x = ftanh(acc2[r*8+4] + bb1.x) + o1.x;
          o1.y = ftanh(acc2[r*8+5] + bb1.y) + o1.y;
          o1.z = ftanh(acc2[r*8+6] + bb1.z) + o1.z;
          o1.w = ftanh(acc2[r*8+7] + bb1.w) + o1.w;
          *(float4*)(rowp) = o0;
          *(float4*)(rowp + 4) = o1;
        }
        __syncwarp();
      }
    }
  }
  // ======================= END DIVERGENT REGION =====================
  __syncthreads();

  // ---- Envelope / orbitals (each half: its own batch) ----
  {
    SmemB* P = half ? P1 : P0;
    int k = th >> 4, i = (th >> 1) & 7, jh = th & 1;
    const float* wrow = envw + (k * 16 + i) * 256;
    float acc[8];
#pragma unroll
    for (int j = 0; j < 8; j++) acc[j] = 0.0f;
    for (int f4 = 0; f4 < 64; f4++) {
      float4 w = __ldg((const float4*)(wrow + f4 * 4));
#pragma unroll
      for (int j = 0; j < 8; j++) {
        float4 a = *(const float4*)(P->one + (jh * 8 + j) * 260 + f4 * 4);
        acc[j] += w.x * a.x + w.y * a.y + w.z * a.z + w.w * a.w;
      }
    }
    float lg = 256.0f * SS->eg[k * 8 + i];
    int si = (k * 8 + i) * 4;
    float p0 = SS->pw[si], p1 = SS->pw[si + 1], p2 = SS->pw[si + 2], p3 = SS->pw[si + 3];
    float s0 = SS->sg[si], s1 = SS->sg[si + 1], s2 = SS->sg[si + 2], s3 = SS->sg[si + 3];
#pragma unroll
    for (int j = 0; j < 8; j++) {
      int col = jh * 8 + j;
      const float* rrow = P->rr + col * 4;
      float env = p0 * __expf(-s0 * rrow[0]) + p1 * __expf(-s1 * rrow[1]) +
                  p2 * __expf(-s2 * rrow[2]) + p3 * __expf(-s3 * rrow[3]);
      P->two4[(jh * 16 + k) * 65 + i * 8 + j] = (acc[j] + lg) * env;
    }
  }
  __syncthreads();

  // ---- Determinants: 32 matrices 8x8 per batch, pivoted LU (warp 0 of each half) ----
  {
    SmemB* P = half ? P1 : P0;
    float* D = P->two4;
    if (th < 32) {
      float* A = D + th * 65;
      float dv = 1.0f;
      for (int cph = 0; cph < 8; cph++) {
        int p = cph; float mx = fabsf(A[cph * 8 + cph]);
        for (int r = cph + 1; r < 8; r++) {
          float fv = fabsf(A[r * 8 + cph]);
          if (fv > mx) { mx = fv; p = r; }
        }
        if (mx == 0.0f) { dv = 0.0f; break; }
        if (p != cph) {
#pragma unroll
          for (int cc = 0; cc < 8; cc++) {
            float t = A[cph * 8 + cc]; A[cph * 8 + cc] = A[p * 8 + cc]; A[p * 8 + cc] = t;
          }
          dv = -dv;
        }
        float piv = A[cph * 8 + cph];
        dv *= piv;
        float inv = 1.0f / piv;
        for (int r = cph + 1; r < 8; r++) {
          float m = A[r * 8 + cph] * inv;
          for (int cc = cph + 1; cc < 8; cc++) A[r * 8 + cc] -= m * A[cph * 8 + cc];
        }
      }
      (D + 2080)[th] = dv;
      __syncwarp();
      if (th < 16) (D + 2112)[th] = (D + 2080)[th] * (D + 2080)[16 + th];
      __syncwarp();
      if (th == 0) {
        float s = 0.0f;
#pragma unroll
        for (int k = 0; k < 16; k++) s += (D + 2112)[k];
        out[half ? b1 : b0] = s;
      }
    }
  }
}

}  // namespace FN

extern "C" void kernel_launch(void* const* d_in, const int* in_sizes, int n_in,
                              void* d_out, int out_size) {
  const float* x    = (const float*)d_in[0];
  const float* nuc  = (const float*)d_in[1];
  const float* v0w  = (const float*)d_in[2];
  const float* v0b  = (const float*)d_in[3];
  const float* vw   = (const float*)d_in[4];
  const float* vb   = (const float*)d_in[5];
  const float* w0w  = (const float*)d_in[6];
  const float* w0b  = (const float*)d_in[7];
  const float* ww   = (const float*)d_in[8];
  const float* wb   = (const float*)d_in[9];
  const float* envw = (const float*)d_in[10];
  const float* envg = (const float*)d_in[11];
  const float* sig  = (const float*)d_in[12];
  const float* pi   = (const float*)d_in[13];
  float* out = (float*)d_out;

  int B = in_sizes[0] / 48;
  int smem = (int)(sizeof(FN::SmemS) + 2 * sizeof(FN::SmemB));
  cudaFuncSetAttribute(FN::ferminet_kernel, cudaFuncAttributeMaxDynamicSharedMemorySize, smem);
  FN::ferminet_kernel<<<B / 2, TPB, smem>>>(x, nuc, v0w, v0b, vw, vb, w0w, w0b, ww, wb,
                                            envw, envg, sig, pi, out);
}